// round 2
// baseline (speedup 1.0000x reference)
#include <cuda_runtime.h>
#include <math.h>

#define BB 32
#define CC 256
#define NN 1024          // 32*32
#define HH 32
#define WW 32
#define QCH 64           // K*HEADS
#define KCH 16           // K*U
#define VCH 64           // V*U
#define HEADS 4
#define KD 16            // depth K
#define RR 23
#define PADL 11
#define EPSB 1e-5f

// ---------------- scratch ----------------
__device__ float g_q[BB * QCH * NN];          // raw q (pre-BN)
__device__ float g_k[BB * KCH * NN];          // raw k -> softmax in place
__device__ float g_v[BB * VCH * NN];          // raw v (pre-BN)
__device__ float g_lp[(size_t)BB * KD * VCH * NN]; // lambda_p, 134 MB
__device__ float g_lc[BB * KD * VCH];         // lambda_c
__device__ float g_qs[QCH], g_qb[QCH];        // folded BN scale/shift for q
__device__ float g_vs[VCH], g_vb[VCH];        // folded BN scale/shift for v

// ---------------- K1: fused 1x1 projections ----------------
// grid (16 ntiles, 3 chtiles, 32 b), 256 threads. Tile: 48 ch x 64 n, thread 3x4.
__global__ __launch_bounds__(256) void k_project(
    const float* __restrict__ x, const float* __restrict__ Wq,
    const float* __restrict__ Wk, const float* __restrict__ Wv)
{
    int b = blockIdx.z, ct = blockIdx.y, nt = blockIdx.x;
    int n0 = nt * 64, ch0 = ct * 48;
    __shared__ float xs[16][64];
    __shared__ float ws[48][17];
    int tid = threadIdx.x;
    int tx = tid & 15, ty = tid >> 4;
    float acc[3][4] = {};
    const float* xb = x + (size_t)b * CC * NN;

    for (int c0 = 0; c0 < CC; c0 += 16) {
        for (int i = tid; i < 16 * 64; i += 256) {
            int cc = i >> 6, nn = i & 63;
            xs[cc][nn] = xb[(size_t)(c0 + cc) * NN + n0 + nn];
        }
        for (int i = tid; i < 48 * 16; i += 256) {
            int r = i >> 4, cc = i & 15;
            int ch = ch0 + r;
            const float* Wp; int row;
            if (ch < 64)      { Wp = Wq; row = ch; }
            else if (ch < 80) { Wp = Wk; row = ch - 64; }
            else              { Wp = Wv; row = ch - 80; }
            ws[r][cc] = Wp[row * CC + c0 + cc];
        }
        __syncthreads();
        #pragma unroll
        for (int cc = 0; cc < 16; cc++) {
            float4 xr = *reinterpret_cast<const float4*>(&xs[cc][tx * 4]);
            float wr0 = ws[ty * 3 + 0][cc];
            float wr1 = ws[ty * 3 + 1][cc];
            float wr2 = ws[ty * 3 + 2][cc];
            acc[0][0] += wr0 * xr.x; acc[0][1] += wr0 * xr.y; acc[0][2] += wr0 * xr.z; acc[0][3] += wr0 * xr.w;
            acc[1][0] += wr1 * xr.x; acc[1][1] += wr1 * xr.y; acc[1][2] += wr1 * xr.z; acc[1][3] += wr1 * xr.w;
            acc[2][0] += wr2 * xr.x; acc[2][1] += wr2 * xr.y; acc[2][2] += wr2 * xr.z; acc[2][3] += wr2 * xr.w;
        }
        __syncthreads();
    }
    #pragma unroll
    for (int i = 0; i < 3; i++) {
        int ch = ch0 + ty * 3 + i;
        #pragma unroll
        for (int j = 0; j < 4; j++) {
            int n = n0 + tx * 4 + j;
            float val = acc[i][j];
            if (ch < 64)      g_q[(((size_t)b * 64 + ch) << 10) + n] = val;
            else if (ch < 80) g_k[(((size_t)b * 16 + (ch - 64)) << 10) + n] = val;
            else              g_v[(((size_t)b * 64 + (ch - 80)) << 10) + n] = val;
        }
    }
}

// ---------------- K2a: BN stats -> folded scale/shift ----------------
// grid 128 blocks (0..63 q channels, 64..127 v channels), 256 threads.
__global__ __launch_bounds__(256) void k_bnstats(
    const float* __restrict__ bnw_q, const float* __restrict__ bnb_q,
    const float* __restrict__ bnw_v, const float* __restrict__ bnb_v)
{
    int ch = blockIdx.x;
    int tid = threadIdx.x;
    const float* src = (ch < 64) ? (g_q + (size_t)ch * NN) : (g_v + (size_t)(ch - 64) * NN);
    float s = 0.f, s2 = 0.f;
    for (int i = tid; i < BB * NN; i += 256) {
        int b = i >> 10, n = i & 1023;
        float v = src[((size_t)b * 64 << 10) + n];
        s += v; s2 += v * v;
    }
    __shared__ float rs[256], rs2[256];
    rs[tid] = s; rs2[tid] = s2;
    __syncthreads();
    for (int st = 128; st > 0; st >>= 1) {
        if (tid < st) { rs[tid] += rs[tid + st]; rs2[tid] += rs2[tid + st]; }
        __syncthreads();
    }
    if (tid == 0) {
        float inv = 1.f / (float)(BB * NN);
        float mean = rs[0] * inv;
        float var = rs2[0] * inv - mean * mean;
        float w, bsh;
        if (ch < 64) { w = bnw_q[ch]; bsh = bnb_q[ch]; }
        else         { w = bnw_v[ch - 64]; bsh = bnb_v[ch - 64]; }
        float sc = w * rsqrtf(var + EPSB);
        float sh = bsh - mean * sc;
        if (ch < 64) { g_qs[ch] = sc; g_qb[ch] = sh; }
        else         { g_vs[ch - 64] = sc; g_vb[ch - 64] = sh; }
    }
}

// ---------------- K2b: softmax over n per (b,k) ----------------
__global__ __launch_bounds__(256) void k_softmax()
{
    int row = blockIdx.x;            // b*16+k
    float* p = g_k + ((size_t)row << 10);
    int tid = threadIdx.x;
    float v0 = p[tid], v1 = p[tid + 256], v2 = p[tid + 512], v3 = p[tid + 768];
    __shared__ float red[256];
    float mx = fmaxf(fmaxf(v0, v1), fmaxf(v2, v3));
    red[tid] = mx; __syncthreads();
    for (int st = 128; st > 0; st >>= 1) {
        if (tid < st) red[tid] = fmaxf(red[tid], red[tid + st]);
        __syncthreads();
    }
    mx = red[0]; __syncthreads();
    v0 = expf(v0 - mx); v1 = expf(v1 - mx); v2 = expf(v2 - mx); v3 = expf(v3 - mx);
    red[tid] = v0 + v1 + v2 + v3; __syncthreads();
    for (int st = 128; st > 0; st >>= 1) {
        if (tid < st) red[tid] += red[tid + st];
        __syncthreads();
    }
    float inv = 1.f / red[0];
    p[tid] = v0 * inv; p[tid + 256] = v1 * inv; p[tid + 512] = v2 * inv; p[tid + 768] = v3 * inv;
}

// ---------------- K3: lambda_c[b,k,v] = sum_n sm*v_bn ----------------
// 32 blocks (one per b), 256 threads = (s in 0..3, v in 0..63)
__global__ __launch_bounds__(256) void k_lambdac()
{
    int b = blockIdx.x;
    int tid = threadIdx.x;
    int s = tid >> 6, v = tid & 63;
    __shared__ float sbuf[16 * 128 + 128 * 65];   // sm_s | vs_s (pitch 65)
    float* sm_s = sbuf;
    float* vs_s = sbuf + 16 * 128;

    float acc[16] = {};
    for (int nc = 0; nc < NN; nc += 128) {
        for (int i = tid; i < 16 * 128; i += 256) {
            int k = i >> 7, nn = i & 127;
            sm_s[k * 128 + nn] = g_k[(((size_t)b * 16 + k) << 10) + nc + nn];
        }
        for (int i = tid; i < 64 * 128; i += 256) {
            int vv = i >> 7, nn = i & 127;
            vs_s[nn * 65 + vv] = g_v[(((size_t)b * 64 + vv) << 10) + nc + nn] * g_vs[vv] + g_vb[vv];
        }
        __syncthreads();
        for (int nn = s * 32; nn < s * 32 + 32; nn++) {
            float vv = vs_s[nn * 65 + v];
            #pragma unroll
            for (int k = 0; k < 16; k++) acc[k] += sm_s[k * 128 + nn] * vv;
        }
        __syncthreads();
    }
    // cross-s reduce in smem (reuse sbuf)
    #pragma unroll
    for (int k = 0; k < 16; k++) sbuf[s * 1024 + k * 64 + v] = acc[k];
    __syncthreads();
    for (int e = tid; e < 1024; e += 256)
        g_lc[b * 1024 + e] = sbuf[e] + sbuf[1024 + e] + sbuf[2048 + e] + sbuf[3072 + e];
}

// ---------------- K4: position conv lambda_p ----------------
// grid (v=64, b=32). Block: image (54x55 padded) + 16x529 embedding in smem.
// Each thread: 4 tasks of (k, row, 16-col half) with 38-wide register window.
__global__ __launch_bounds__(256) void k_conv(const float* __restrict__ emb)
{
    int v = blockIdx.x, b = blockIdx.y;
    __shared__ float img[54 * 55];
    __shared__ float Es[16 * 529];
    int tid = threadIdx.x;
    for (int i = tid; i < 54 * 55; i += 256) img[i] = 0.f;
    for (int i = tid; i < 16 * 529; i += 256) Es[i] = emb[i];
    __syncthreads();
    float vsc = g_vs[v], vsh = g_vb[v];
    const float* src = g_v + (((size_t)b * 64 + v) << 10);
    for (int i = tid; i < 1024; i += 256) {
        int y = i >> 5, x = i & 31;
        img[(y + PADL) * 55 + x + PADL] = src[i] * vsc + vsh;
    }
    __syncthreads();

    for (int it = 0; it < 4; it++) {
        int task = tid + 256 * it;
        int k = task >> 6;
        int rh = task & 63;
        int row = rh >> 1;
        int xb = (rh & 1) << 4;
        float acc[16] = {};
        const float* ek = Es + k * 529;
        #pragma unroll 1
        for (int i = 0; i < RR; i++) {
            const float* rp = img + (row + i) * 55 + xb;
            float r[38];
            #pragma unroll
            for (int t = 0; t < 38; t++) r[t] = rp[t];
            const float* ept = ek + i * RR;
            #pragma unroll
            for (int j = 0; j < RR; j++) {
                float e = ept[j];
                #pragma unroll
                for (int x = 0; x < 16; x++) acc[x] += e * r[j + x];
            }
        }
        float* o = g_lp + ((((size_t)b * 16 + k) * 64 + v) << 10) + row * 32 + xb;
        #pragma unroll
        for (int x = 0; x < 16; x++) o[x] = acc[x];
    }
}

// ---------------- K5: final fused contraction + output ----------------
// grid (4 nchunks, 32 b), 256 threads; thread = one n position.
__global__ __launch_bounds__(256) void k_final(const float* __restrict__ gamma,
                                               float* __restrict__ out)
{
    int b = blockIdx.y;
    int n = blockIdx.x * 256 + threadIdx.x;
    __shared__ float lc_s[1024];
    for (int i = threadIdx.x; i < 1024; i += 256) lc_s[i] = g_lc[b * 1024 + i];
    __syncthreads();
    float qv[64];
    #pragma unroll
    for (int ch = 0; ch < 64; ch++)
        qv[ch] = g_q[(((size_t)b * 64 + ch) << 10) + n] * g_qs[ch] + g_qb[ch];
    float gm = 1.f + gamma[0];
    const float* lpb = g_lp + (((size_t)b * 16 * 64) << 10) + n;
    for (int v = 0; v < 64; v++) {
        float m[16];
        #pragma unroll
        for (int k = 0; k < 16; k++)
            m[k] = lc_s[k * 64 + v] + lpb[((size_t)(k * 64 + v)) << 10];
        #pragma unroll
        for (int h = 0; h < 4; h++) {
            float r = 0.f;
            #pragma unroll
            for (int k = 0; k < 16; k++) r += qv[h * 16 + k] * m[k];
            out[(((size_t)b * 256) + h * 64 + v) * NN + n] = r * gm;
        }
    }
}

// ---------------- launch ----------------
extern "C" void kernel_launch(void* const* d_in, const int* in_sizes, int n_in,
                              void* d_out, int out_size)
{
    const float* x      = (const float*)d_in[0];
    const float* Wq     = (const float*)d_in[1];
    const float* bn_q_w = (const float*)d_in[2];
    const float* bn_q_b = (const float*)d_in[3];
    const float* Wk     = (const float*)d_in[4];
    const float* Wv     = (const float*)d_in[5];
    const float* bn_v_w = (const float*)d_in[6];
    const float* bn_v_b = (const float*)d_in[7];
    const float* emb    = (const float*)d_in[8];
    const float* gamma  = (const float*)d_in[9];
    float* out = (float*)d_out;

    k_project<<<dim3(16, 3, 32), 256>>>(x, Wq, Wk, Wv);
    k_bnstats<<<128, 256>>>(bn_q_w, bn_q_b, bn_v_w, bn_v_b);
    k_softmax<<<512, 256>>>();
    k_lambdac<<<32, 256>>>();
    k_conv<<<dim3(64, 32), 256>>>(emb);
    k_final<<<dim3(4, 32), 256>>>(gamma, out);
}

// round 4
// speedup vs baseline: 2.0488x; 2.0488x over previous
#include <cuda_runtime.h>
#include <cuda_fp16.h>
#include <cstdint>
#include <math.h>

#define BB 32
#define CC 256
#define NN 1024
#define QCH 64
#define KCH 16
#define VCH 64
#define HEADS 4
#define KD 16
#define RR 23
#define PADL 11
#define EPSB 1e-5f

// arch-specific (tcgen05-capable) compilation pass?
#if defined(__CUDA_ARCH_FEAT_SM103_ALL) || defined(__CUDA_ARCH_FEAT_SM100_ALL) || \
    defined(__CUDA_ARCH_FEAT_SM101_ALL) || defined(__CUDA_ARCH_SPECIFIC__) || \
    defined(__CUDA_ARCH_FAMILY_SPECIFIC__)
#define USE_TC 1
#else
#define USE_TC 0
#endif

// ---------------- scratch ----------------
__device__ float g_q[BB * QCH * NN];
__device__ float g_k[BB * KCH * NN];
__device__ float g_v[BB * VCH * NN];
__device__ float g_lp[(size_t)BB * KD * VCH * NN];
__device__ float g_lc[BB * KD * VCH];
__device__ float g_lcp[8][BB * KD * VCH];
__device__ float g_qs[QCH], g_qb[QCH];
__device__ float g_vs[VCH], g_vb[VCH];
__device__ __half g_T[(size_t)16 * 1024 * 1024]; // Toeplitz conv matrix, fp16, 32MB
__device__ __half g_vh[(size_t)2048 * 1024];     // BN'd v in fp16, [bv][m]

// ---------------- PTX helpers ----------------
__device__ __forceinline__ uint32_t smem_u32(const void* p) {
    uint32_t r;
    asm("{ .reg .u64 t; cvta.to.shared.u64 t, %1; cvt.u32.u64 %0, t; }" : "=r"(r) : "l"(p));
    return r;
}
__device__ __forceinline__ void cpasync16(uint32_t s, const void* g) {
    asm volatile("cp.async.cg.shared.global [%0], [%1], 16;" :: "r"(s), "l"(g));
}
#define CP_COMMIT()  asm volatile("cp.async.commit_group;" ::: "memory")
#define CP_WAIT1()   asm volatile("cp.async.wait_group 1;" ::: "memory")

#if USE_TC
__device__ __forceinline__ uint32_t elect1() {
    uint32_t p;
    asm volatile("{ .reg .pred p; elect.sync _|p, 0xFFFFFFFF; selp.b32 %0,1,0,p; }" : "=r"(p));
    return p;
}
#define MBAR_INIT(a, c) asm volatile("mbarrier.init.shared.b64 [%0], %1;" :: "r"(a), "r"(c) : "memory")
#define MBAR_INVAL(a)   asm volatile("mbarrier.inval.shared.b64 [%0];" :: "r"(a) : "memory")
#define MBAR_WAIT(a, ph) do { \
    uint32_t _m = (a), _p = (ph), _d; \
    asm volatile("{ .reg .pred p; mbarrier.try_wait.parity.acquire.cta.shared::cta.b64 p, [%1], %2; selp.b32 %0,1,0,p; }" \
        : "=r"(_d) : "r"(_m), "r"(_p) : "memory"); \
    if (!_d) { \
        asm volatile("{ .reg .pred P1; WL_%=: mbarrier.try_wait.parity.acquire.cta.shared::cta.b64 P1, [%0], %1, 0x989680; @P1 bra.uni WD_%=; bra.uni WL_%=; WD_%=: }" \
            :: "r"(_m), "r"(_p) : "memory"); \
    } } while (0)

#define TC_ALLOC(sa, n)   asm volatile("tcgen05.alloc.cta_group::1.sync.aligned.shared::cta.b32 [%0], %1;" :: "r"(sa), "r"(n) : "memory")
#define TC_DEALLOC(t, n)  asm volatile("tcgen05.dealloc.cta_group::1.sync.aligned.b32 %0, %1;" :: "r"(t), "r"(n))
#define TC_RELINQ()       asm volatile("tcgen05.relinquish_alloc_permit.cta_group::1.sync.aligned;")
#define TC_COMMIT(mb)     asm volatile("tcgen05.commit.cta_group::1.mbarrier::arrive::one.shared::cluster.b64 [%0];" :: "r"(mb) : "memory")
#define TC_FENCE_AFTER()  asm volatile("tcgen05.fence::after_thread_sync;" ::: "memory")
#define TC_WAIT_LD()      asm volatile("tcgen05.wait::ld.sync.aligned;" ::: "memory")
#define FENCE_ASYNC()     asm volatile("fence.proxy.async.shared::cta;" ::: "memory")

#define TC_LD_X32(r, t) \
    asm volatile("tcgen05.ld.sync.aligned.32x32b.x32.b32 " \
        "{%0,%1,%2,%3,%4,%5,%6,%7,%8,%9,%10,%11,%12,%13,%14,%15," \
        "%16,%17,%18,%19,%20,%21,%22,%23,%24,%25,%26,%27,%28,%29,%30,%31}, [%32];" \
        : "=r"((r)[0]),"=r"((r)[1]),"=r"((r)[2]),"=r"((r)[3]),"=r"((r)[4]),"=r"((r)[5]),"=r"((r)[6]),"=r"((r)[7]), \
          "=r"((r)[8]),"=r"((r)[9]),"=r"((r)[10]),"=r"((r)[11]),"=r"((r)[12]),"=r"((r)[13]),"=r"((r)[14]),"=r"((r)[15]), \
          "=r"((r)[16]),"=r"((r)[17]),"=r"((r)[18]),"=r"((r)[19]),"=r"((r)[20]),"=r"((r)[21]),"=r"((r)[22]),"=r"((r)[23]), \
          "=r"((r)[24]),"=r"((r)[25]),"=r"((r)[26]),"=r"((r)[27]),"=r"((r)[28]),"=r"((r)[29]),"=r"((r)[30]),"=r"((r)[31]) \
        : "r"(t))

__device__ __forceinline__ void mma_f16_ss(uint32_t d, uint64_t ad, uint64_t bd,
                                           uint32_t idesc, uint32_t en) {
    asm volatile(
        "{ .reg .pred p; setp.ne.u32 p, %4, 0;\n\t"
        "tcgen05.mma.cta_group::1.kind::f16 [%0], %1, %2, %3, {%5,%5,%5,%5}, p;\n\t}"
        :: "r"(d), "l"(ad), "l"(bd), "r"(idesc), "r"(en), "r"(0u) : "memory");
}

static constexpr uint64_t DESC_BASE =
    (uint64_t(2) << 61) | (uint64_t(1) << 46) | (uint64_t(64) << 32) | (uint64_t(1) << 16);
__device__ __forceinline__ uint64_t mk_desc(uint32_t a) {
    return DESC_BASE | ((uint64_t)(a >> 4) & 0x3FFF);
}
#endif // USE_TC

// ---------------- K1: fused 1x1 projections ----------------
__global__ __launch_bounds__(256) void k_project(
    const float* __restrict__ x, const float* __restrict__ Wq,
    const float* __restrict__ Wk, const float* __restrict__ Wv)
{
    int b = blockIdx.z, ct = blockIdx.y, nt = blockIdx.x;
    int n0 = nt * 64, ch0 = ct * 48;
    __shared__ float xs[16][64];
    __shared__ float ws[48][17];
    int tid = threadIdx.x;
    int tx = tid & 15, ty = tid >> 4;
    float acc[3][4] = {};
    const float* xb = x + (size_t)b * CC * NN;

    for (int c0 = 0; c0 < CC; c0 += 16) {
        for (int i = tid; i < 16 * 64; i += 256) {
            int cc = i >> 6, nn = i & 63;
            xs[cc][nn] = xb[(size_t)(c0 + cc) * NN + n0 + nn];
        }
        for (int i = tid; i < 48 * 16; i += 256) {
            int r = i >> 4, cc = i & 15;
            int ch = ch0 + r;
            const float* Wp; int row;
            if (ch < 64)      { Wp = Wq; row = ch; }
            else if (ch < 80) { Wp = Wk; row = ch - 64; }
            else              { Wp = Wv; row = ch - 80; }
            ws[r][cc] = Wp[row * CC + c0 + cc];
        }
        __syncthreads();
        #pragma unroll
        for (int cc = 0; cc < 16; cc++) {
            float4 xr = *reinterpret_cast<const float4*>(&xs[cc][tx * 4]);
            float wr0 = ws[ty * 3 + 0][cc];
            float wr1 = ws[ty * 3 + 1][cc];
            float wr2 = ws[ty * 3 + 2][cc];
            acc[0][0] += wr0 * xr.x; acc[0][1] += wr0 * xr.y; acc[0][2] += wr0 * xr.z; acc[0][3] += wr0 * xr.w;
            acc[1][0] += wr1 * xr.x; acc[1][1] += wr1 * xr.y; acc[1][2] += wr1 * xr.z; acc[1][3] += wr1 * xr.w;
            acc[2][0] += wr2 * xr.x; acc[2][1] += wr2 * xr.y; acc[2][2] += wr2 * xr.z; acc[2][3] += wr2 * xr.w;
        }
        __syncthreads();
    }
    #pragma unroll
    for (int i = 0; i < 3; i++) {
        int ch = ch0 + ty * 3 + i;
        #pragma unroll
        for (int j = 0; j < 4; j++) {
            int n = n0 + tx * 4 + j;
            float val = acc[i][j];
            if (ch < 64)      g_q[(((size_t)b * 64 + ch) << 10) + n] = val;
            else if (ch < 80) g_k[(((size_t)b * 16 + (ch - 64)) << 10) + n] = val;
            else              g_v[(((size_t)b * 64 + (ch - 80)) << 10) + n] = val;
        }
    }
}

// ---------------- K2a: BN stats ----------------
__global__ __launch_bounds__(256) void k_bnstats(
    const float* __restrict__ bnw_q, const float* __restrict__ bnb_q,
    const float* __restrict__ bnw_v, const float* __restrict__ bnb_v)
{
    int ch = blockIdx.x;
    int tid = threadIdx.x;
    const float* src = (ch < 64) ? (g_q + (size_t)ch * NN) : (g_v + (size_t)(ch - 64) * NN);
    float s = 0.f, s2 = 0.f;
    for (int i = tid; i < BB * NN; i += 256) {
        int b = i >> 10, n = i & 1023;
        float v = src[((size_t)b * 64 << 10) + n];
        s += v; s2 += v * v;
    }
    __shared__ float rs[256], rs2[256];
    rs[tid] = s; rs2[tid] = s2;
    __syncthreads();
    for (int st = 128; st > 0; st >>= 1) {
        if (tid < st) { rs[tid] += rs[tid + st]; rs2[tid] += rs2[tid + st]; }
        __syncthreads();
    }
    if (tid == 0) {
        float inv = 1.f / (float)(BB * NN);
        float mean = rs[0] * inv;
        float var = rs2[0] * inv - mean * mean;
        float w, bsh;
        if (ch < 64) { w = bnw_q[ch]; bsh = bnb_q[ch]; }
        else         { w = bnw_v[ch - 64]; bsh = bnb_v[ch - 64]; }
        float sc = w * rsqrtf(var + EPSB);
        float sh = bsh - mean * sc;
        if (ch < 64) { g_qs[ch] = sc; g_qb[ch] = sh; }
        else         { g_vs[ch - 64] = sc; g_vb[ch - 64] = sh; }
    }
}

// ---------------- K2b: softmax ----------------
__global__ __launch_bounds__(256) void k_softmax()
{
    int row = blockIdx.x;
    float* p = g_k + ((size_t)row << 10);
    int tid = threadIdx.x;
    float v0 = p[tid], v1 = p[tid + 256], v2 = p[tid + 512], v3 = p[tid + 768];
    __shared__ float red[256];
    float mx = fmaxf(fmaxf(v0, v1), fmaxf(v2, v3));
    red[tid] = mx; __syncthreads();
    for (int st = 128; st > 0; st >>= 1) {
        if (tid < st) red[tid] = fmaxf(red[tid], red[tid + st]);
        __syncthreads();
    }
    mx = red[0]; __syncthreads();
    v0 = expf(v0 - mx); v1 = expf(v1 - mx); v2 = expf(v2 - mx); v3 = expf(v3 - mx);
    red[tid] = v0 + v1 + v2 + v3; __syncthreads();
    for (int st = 128; st > 0; st >>= 1) {
        if (tid < st) red[tid] += red[tid + st];
        __syncthreads();
    }
    float inv = 1.f / red[0];
    p[tid] = v0 * inv; p[tid + 256] = v1 * inv; p[tid + 512] = v2 * inv; p[tid + 768] = v3 * inv;
}

// ---------------- K3: lambda_c partials ----------------
__global__ __launch_bounds__(256) void k_lambdac()
{
    int b = blockIdx.x;
    int part = blockIdx.y;
    int nc = part * 128;
    int tid = threadIdx.x;
    int s = tid >> 6, v = tid & 63;
    __shared__ float sbuf[16 * 128 + 128 * 65];
    float* sm_s = sbuf;
    float* vs_s = sbuf + 16 * 128;

    for (int i = tid; i < 16 * 128; i += 256) {
        int k = i >> 7, nn = i & 127;
        sm_s[k * 128 + nn] = g_k[(((size_t)b * 16 + k) << 10) + nc + nn];
    }
    for (int i = tid; i < 64 * 128; i += 256) {
        int vv = i >> 7, nn = i & 127;
        vs_s[nn * 65 + vv] = g_v[(((size_t)b * 64 + vv) << 10) + nc + nn] * g_vs[vv] + g_vb[vv];
    }
    __syncthreads();
    float acc[16] = {};
    for (int nn = s * 32; nn < s * 32 + 32; nn++) {
        float vv = vs_s[nn * 65 + v];
        #pragma unroll
        for (int k = 0; k < 16; k++) acc[k] += sm_s[k * 128 + nn] * vv;
    }
    __syncthreads();
    #pragma unroll
    for (int k = 0; k < 16; k++) sbuf[s * 1024 + k * 64 + v] = acc[k];
    __syncthreads();
    for (int e = tid; e < 1024; e += 256)
        g_lcp[part][b * 1024 + e] = sbuf[e] + sbuf[1024 + e] + sbuf[2048 + e] + sbuf[3072 + e];
}

__global__ __launch_bounds__(256) void k_lcred()
{
    int i = blockIdx.x * 256 + threadIdx.x;
    float s = 0.f;
    #pragma unroll
    for (int p = 0; p < 8; p++) s += g_lcp[p][i];
    g_lc[i] = s;
}

// ---------------- K4a: build fp16 Toeplitz matrix T ----------------
__global__ __launch_bounds__(256) void k_buildT(const float* __restrict__ emb)
{
    size_t i = (size_t)blockIdx.x * 256 + threadIdx.x;
    int k = (int)(i >> 19);
    int rem = (int)(i & 0x7FFFF);
    int n = rem >> 9;
    int m0 = (rem & 511) * 2;
    int yn = n >> 5, xn = n & 31;
    float f[2];
    #pragma unroll
    for (int e = 0; e < 2; e++) {
        int mm = m0 + e;
        int dy = (mm >> 5) - yn + 11;
        int dx = (mm & 31) - xn + 11;
        f[e] = ((unsigned)dy < 23u && (unsigned)dx < 23u) ? emb[k * 529 + dy * 23 + dx] : 0.f;
    }
    __half2 h = __floats2half2_rn(f[0], f[1]);
    *reinterpret_cast<__half2*>(g_T + (((size_t)k << 20) + ((size_t)n << 10) + m0)) = h;
}

// ---------------- K4b: BN'd v in fp16 ----------------
__global__ __launch_bounds__(256) void k_vhalf()
{
    int bv = blockIdx.x;
    int v = bv & 63;
    float sc = g_vs[v], sh = g_vb[v];
    const float* src = g_v + ((size_t)bv << 10);
    __half* dst = g_vh + ((size_t)bv << 10);
    for (int i = threadIdx.x; i < 1024; i += 256)
        dst[i] = __float2half(src[i] * sc + sh);
}

// ---------------- K5: lambda_p (+lambda_c) ----------------
// TC path: tcgen05 fp16 GEMM, tile 128n x 256bv, K=1024 in 64-chunks.
// Fallback path (non-arch-specific compile): scalar direct conv (known good).
#define GEMM_SMEM (1024 + 2 * 16384 + 2 * 32768)

__global__ __launch_bounds__(128) void k_gemm(const float* __restrict__ emb)
{
#if USE_TC
    extern __shared__ char dsm[];
    __shared__ __align__(16) uint64_t s_mbar[2];
    __shared__ uint32_t s_tmem;

    int tid = threadIdx.x;
    int wid = tid >> 5, lane = tid & 31;
    int kk = blockIdx.z;
    int n0 = blockIdx.x * 128;
    int bv0 = blockIdx.y * 256;

    uint32_t raw = smem_u32(dsm);
    uint32_t abase = (raw + 1023) & ~1023u;

    if (wid == 0) {
        TC_ALLOC(smem_u32(&s_tmem), 256);
        TC_RELINQ();
    }
    if (tid == 0) { MBAR_INIT(smem_u32(&s_mbar[0]), 1); MBAR_INIT(smem_u32(&s_mbar[1]), 1); }
    __syncthreads();
    uint32_t tmem = s_tmem;

    const __half* Tk = g_T + ((size_t)kk << 20);

    #define ISSUE_LOADS(chunk, stage) do {                                          \
        int _m0 = (chunk) * 64;                                                     \
        uint32_t _Ab = abase + (stage) * 16384;                                     \
        uint32_t _Bb = abase + 32768 + (stage) * 32768;                             \
        for (int _i = tid; _i < 1024; _i += 128) {                                  \
            int _r = _i >> 3, _c = _i & 7;                                          \
            uint32_t _o = _r * 128 + _c * 16;                                       \
            uint32_t _s = _o ^ ((_o >> 3) & 0x70);                                  \
            cpasync16(_Ab + _s, Tk + (((size_t)(n0 + _r) << 10) + _m0 + _c * 8));   \
        }                                                                           \
        for (int _i = tid; _i < 2048; _i += 128) {                                  \
            int _r = _i >> 3, _c = _i & 7;                                          \
            uint32_t _o = _r * 128 + _c * 16;                                       \
            uint32_t _s = _o ^ ((_o >> 3) & 0x70);                                  \
            cpasync16(_Bb + _s, g_vh + (((size_t)(bv0 + _r) << 10) + _m0 + _c * 8)); \
        }                                                                           \
    } while (0)

    ISSUE_LOADS(0, 0); CP_COMMIT();
    ISSUE_LOADS(1, 1); CP_COMMIT();

    const uint32_t idesc = (1u << 4) | (32u << 17) | (8u << 24);  // F32 acc, f16, N=256, M=128
    uint32_t ph0 = 0, ph1 = 0;

    for (int c = 0; c < 16; c++) {
        int s = c & 1;
        CP_WAIT1();
        __syncthreads();
        if (wid == 0) {
            FENCE_ASYNC();
            if (elect1()) {
                uint64_t ad = mk_desc(abase + s * 16384);
                uint64_t bd = mk_desc(abase + 32768 + s * 32768);
                #pragma unroll
                for (int ks = 0; ks < 4; ks++)
                    mma_f16_ss(tmem, ad + ks * 2, bd + ks * 2, idesc, (c | ks) != 0);
                TC_COMMIT(smem_u32(&s_mbar[s]));
            }
        }
        uint32_t ph = s ? ph1 : ph0;
        MBAR_WAIT(smem_u32(&s_mbar[s]), ph);
        if (s) ph1 ^= 1; else ph0 ^= 1;
        if (c + 2 < 16) { ISSUE_LOADS(c + 2, s); }
        CP_COMMIT();
    }
    TC_FENCE_AFTER();

    int n_g = n0 + wid * 32 + lane;
    for (int c0 = 0; c0 < 256; c0 += 32) {
        uint32_t r[32];
        TC_LD_X32(r, tmem + c0);
        TC_WAIT_LD();
        #pragma unroll
        for (int j = 0; j < 32; j++) {
            int bv = bv0 + c0 + j;
            int b = bv >> 6, v = bv & 63;
            int row = (b * 16 + kk) * 64 + v;
            float lc = g_lc[row];
            g_lp[((size_t)row << 10) + n_g] = __uint_as_float(r[j]) + lc;
        }
    }
    __syncthreads();
    if (tid == 0) { MBAR_INVAL(smem_u32(&s_mbar[0])); MBAR_INVAL(smem_u32(&s_mbar[1])); }
    __syncthreads();
    if (wid == 0) TC_DEALLOC(tmem, 256);
    #undef ISSUE_LOADS

#else  // ---- fallback: scalar direct conv (correct on any target) ----
    extern __shared__ char dsm[];
    float* img = (float*)dsm;            // 54*55
    float* Es  = img + 54 * 55;          // 16*529
    int tid = threadIdx.x;
    int bid = blockIdx.x + blockIdx.y * 8 + blockIdx.z * 64;  // 0..1023

    for (int i = tid; i < 16 * 529; i += 128) Es[i] = emb[i];

    for (int pair = 0; pair < 2; pair++) {
        int bv = bid * 2 + pair;
        int b = bv >> 6, v = bv & 63;
        __syncthreads();
        for (int i = tid; i < 54 * 55; i += 128) img[i] = 0.f;
        __syncthreads();
        float vsc = g_vs[v], vsh = g_vb[v];
        const float* src = g_v + ((size_t)bv << 10);
        for (int i = tid; i < 1024; i += 128) {
            int y = i >> 5, x = i & 31;
            img[(y + PADL) * 55 + x + PADL] = src[i] * vsc + vsh;
        }
        __syncthreads();

        for (int it = 0; it < 8; it++) {
            int task = tid + 128 * it;
            int k = task >> 6;
            int rh = task & 63;
            int row = rh >> 1;
            int xb = (rh & 1) << 4;
            float acc[16] = {};
            const float* ek = Es + k * 529;
            #pragma unroll 1
            for (int i = 0; i < RR; i++) {
                const float* rp = img + (row + i) * 55 + xb;
                float r[38];
                #pragma unroll
                for (int t = 0; t < 38; t++) r[t] = rp[t];
                const float* ept = ek + i * RR;
                #pragma unroll
                for (int j = 0; j < RR; j++) {
                    float e = ept[j];
                    #pragma unroll
                    for (int x = 0; x < 16; x++) acc[x] += e * r[j + x];
                }
            }
            int rowid = (b * 16 + k) * 64 + v;
            float lc = g_lc[rowid];
            float* o = g_lp + ((size_t)rowid << 10) + row * 32 + xb;
            #pragma unroll
            for (int x = 0; x < 16; x++) o[x] = acc[x] + lc;
        }
    }
#endif
}

// ---------------- K6: final contraction ----------------
__global__ __launch_bounds__(256) void k_final(const float* __restrict__ gamma,
                                               float* __restrict__ out)
{
    int b = blockIdx.z;
    int v0 = blockIdx.y * 16;
    int n = blockIdx.x * 256 + threadIdx.x;
    float qv[64];
    #pragma unroll
    for (int ch = 0; ch < 64; ch++)
        qv[ch] = g_q[(((size_t)b * 64 + ch) << 10) + n] * g_qs[ch] + g_qb[ch];
    float gm = 1.f + gamma[0];
    const float* lpb = g_lp + (((size_t)b << 20)) + n;
    for (int v = v0; v < v0 + 16; v++) {
        float m[16];
        #pragma unroll
        for (int k = 0; k < 16; k++)
            m[k] = lpb[((size_t)(k * 64 + v)) << 10];
        #pragma unroll
        for (int h = 0; h < 4; h++) {
            float r = 0.f;
            #pragma unroll
            for (int k = 0; k < 16; k++) r += qv[h * 16 + k] * m[k];
            out[(((size_t)b * 256) + h * 64 + v) * NN + n] = r * gm;
        }
    }
}

// ---------------- launch ----------------
extern "C" void kernel_launch(void* const* d_in, const int* in_sizes, int n_in,
                              void* d_out, int out_size)
{
    const float* x      = (const float*)d_in[0];
    const float* Wq     = (const float*)d_in[1];
    const float* bn_q_w = (const float*)d_in[2];
    const float* bn_q_b = (const float*)d_in[3];
    const float* Wk     = (const float*)d_in[4];
    const float* Wv     = (const float*)d_in[5];
    const float* bn_v_w = (const float*)d_in[6];
    const float* bn_v_b = (const float*)d_in[7];
    const float* emb    = (const float*)d_in[8];
    const float* gamma  = (const float*)d_in[9];
    float* out = (float*)d_out;

    cudaFuncSetAttribute(k_gemm, cudaFuncAttributeMaxDynamicSharedMemorySize, GEMM_SMEM);

    k_buildT<<<32768, 256>>>(emb);
    k_project<<<dim3(16, 3, 32), 256>>>(x, Wq, Wk, Wv);
    k_bnstats<<<128, 256>>>(bn_q_w, bn_q_b, bn_v_w, bn_v_b);
    k_softmax<<<512, 256>>>();
    k_vhalf<<<2048, 256>>>();
    k_lambdac<<<dim3(32, 8), 256>>>();
    k_lcred<<<128, 256>>>();
    k_gemm<<<dim3(8, 8, 16), 128, GEMM_SMEM>>>(emb);
    k_final<<<dim3(4, 4, 32), 256>>>(gamma, out);
}

// round 5
// speedup vs baseline: 2.5526x; 1.2459x over previous
#include <cuda_runtime.h>
#include <cuda_fp16.h>
#include <cstdint>
#include <math.h>

#define BB 32
#define CC 256
#define NN 1024
#define QCH 64
#define KCH 16
#define VCH 64
#define HEADS 4
#define KD 16
#define RR 23
#define PADL 11
#define EPSB 1e-5f

// arch-specific (tcgen05-capable) compilation pass?
#if defined(__CUDA_ARCH_FEAT_SM103_ALL) || defined(__CUDA_ARCH_FEAT_SM100_ALL) || \
    defined(__CUDA_ARCH_FEAT_SM101_ALL) || defined(__CUDA_ARCH_SPECIFIC__) || \
    defined(__CUDA_ARCH_FAMILY_SPECIFIC__)
#define USE_TC 1
#else
#define USE_TC 0
#endif

// ---------------- scratch ----------------
__device__ float g_q[BB * QCH * NN];
__device__ float g_k[BB * KCH * NN];
__device__ float g_v[BB * VCH * NN];
__device__ __half g_lph[(size_t)BB * KD * NN * VCH];   // lambda_p fp16 [b][k][n][v], 67MB
__device__ float g_lc[BB * KD * VCH];
__device__ float g_lcp[8][BB * KD * VCH];
__device__ float g_qs[QCH], g_qb[QCH];
__device__ float g_vs[VCH], g_vb[VCH];
__device__ __half g_T[(size_t)16 * 1024 * 1024];       // Toeplitz conv matrix, fp16, 32MB
__device__ __half g_vh[(size_t)2048 * 1024];           // BN'd v in fp16, [bv][m]

// ---------------- PTX helpers ----------------
__device__ __forceinline__ uint32_t smem_u32(const void* p) {
    uint32_t r;
    asm("{ .reg .u64 t; cvta.to.shared.u64 t, %1; cvt.u32.u64 %0, t; }" : "=r"(r) : "l"(p));
    return r;
}
__device__ __forceinline__ void cpasync16(uint32_t s, const void* g) {
    asm volatile("cp.async.cg.shared.global [%0], [%1], 16;" :: "r"(s), "l"(g));
}
#define CP_COMMIT()  asm volatile("cp.async.commit_group;" ::: "memory")
#define CP_WAIT(n)   asm volatile("cp.async.wait_group %0;" :: "n"(n) : "memory")

#if USE_TC
__device__ __forceinline__ uint32_t elect1() {
    uint32_t p;
    asm volatile("{ .reg .pred p; elect.sync _|p, 0xFFFFFFFF; selp.b32 %0,1,0,p; }" : "=r"(p));
    return p;
}
#define MBAR_INIT(a, c) asm volatile("mbarrier.init.shared.b64 [%0], %1;" :: "r"(a), "r"(c) : "memory")
#define MBAR_INVAL(a)   asm volatile("mbarrier.inval.shared.b64 [%0];" :: "r"(a) : "memory")
#define MBAR_WAIT(a, ph) do { \
    uint32_t _m = (a), _p = (ph), _d; \
    asm volatile("{ .reg .pred p; mbarrier.try_wait.parity.acquire.cta.shared::cta.b64 p, [%1], %2; selp.b32 %0,1,0,p; }" \
        : "=r"(_d) : "r"(_m), "r"(_p) : "memory"); \
    if (!_d) { \
        asm volatile("{ .reg .pred P1; WL_%=: mbarrier.try_wait.parity.acquire.cta.shared::cta.b64 P1, [%0], %1, 0x989680; @P1 bra.uni WD_%=; bra.uni WL_%=; WD_%=: }" \
            :: "r"(_m), "r"(_p) : "memory"); \
    } } while (0)

#define TC_ALLOC(sa, n)   asm volatile("tcgen05.alloc.cta_group::1.sync.aligned.shared::cta.b32 [%0], %1;" :: "r"(sa), "r"(n) : "memory")
#define TC_DEALLOC(t, n)  asm volatile("tcgen05.dealloc.cta_group::1.sync.aligned.b32 %0, %1;" :: "r"(t), "r"(n))
#define TC_RELINQ()       asm volatile("tcgen05.relinquish_alloc_permit.cta_group::1.sync.aligned;")
#define TC_COMMIT(mb)     asm volatile("tcgen05.commit.cta_group::1.mbarrier::arrive::one.shared::cluster.b64 [%0];" :: "r"(mb) : "memory")
#define TC_FENCE_AFTER()  asm volatile("tcgen05.fence::after_thread_sync;" ::: "memory")
#define TC_WAIT_LD()      asm volatile("tcgen05.wait::ld.sync.aligned;" ::: "memory")
#define FENCE_ASYNC()     asm volatile("fence.proxy.async.shared::cta;" ::: "memory")

#define TC_LD_X32(r, t) \
    asm volatile("tcgen05.ld.sync.aligned.32x32b.x32.b32 " \
        "{%0,%1,%2,%3,%4,%5,%6,%7,%8,%9,%10,%11,%12,%13,%14,%15," \
        "%16,%17,%18,%19,%20,%21,%22,%23,%24,%25,%26,%27,%28,%29,%30,%31}, [%32];" \
        : "=r"((r)[0]),"=r"((r)[1]),"=r"((r)[2]),"=r"((r)[3]),"=r"((r)[4]),"=r"((r)[5]),"=r"((r)[6]),"=r"((r)[7]), \
          "=r"((r)[8]),"=r"((r)[9]),"=r"((r)[10]),"=r"((r)[11]),"=r"((r)[12]),"=r"((r)[13]),"=r"((r)[14]),"=r"((r)[15]), \
          "=r"((r)[16]),"=r"((r)[17]),"=r"((r)[18]),"=r"((r)[19]),"=r"((r)[20]),"=r"((r)[21]),"=r"((r)[22]),"=r"((r)[23]), \
          "=r"((r)[24]),"=r"((r)[25]),"=r"((r)[26]),"=r"((r)[27]),"=r"((r)[28]),"=r"((r)[29]),"=r"((r)[30]),"=r"((r)[31]) \
        : "r"(t))

__device__ __forceinline__ void mma_f16_ss(uint32_t d, uint64_t ad, uint64_t bd,
                                           uint32_t idesc, uint32_t en) {
    asm volatile(
        "{ .reg .pred p; setp.ne.u32 p, %4, 0;\n\t"
        "tcgen05.mma.cta_group::1.kind::f16 [%0], %1, %2, %3, {%5,%5,%5,%5}, p;\n\t}"
        :: "r"(d), "l"(ad), "l"(bd), "r"(idesc), "r"(en), "r"(0u) : "memory");
}

static constexpr uint64_t DESC_BASE =
    (uint64_t(2) << 61) | (uint64_t(1) << 46) | (uint64_t(64) << 32) | (uint64_t(1) << 16);
__device__ __forceinline__ uint64_t mk_desc(uint32_t a) {
    return DESC_BASE | ((uint64_t)(a >> 4) & 0x3FFF);
}
#endif // USE_TC

// ---------------- K1: fused 1x1 projections ----------------
__global__ __launch_bounds__(256) void k_project(
    const float* __restrict__ x, const float* __restrict__ Wq,
    const float* __restrict__ Wk, const float* __restrict__ Wv)
{
    int b = blockIdx.z, ct = blockIdx.y, nt = blockIdx.x;
    int n0 = nt * 64, ch0 = ct * 48;
    __shared__ float xs[16][64];
    __shared__ float ws[48][17];
    int tid = threadIdx.x;
    int tx = tid & 15, ty = tid >> 4;
    float acc[3][4] = {};
    const float* xb = x + (size_t)b * CC * NN;

    for (int c0 = 0; c0 < CC; c0 += 16) {
        for (int i = tid; i < 16 * 64; i += 256) {
            int cc = i >> 6, nn = i & 63;
            xs[cc][nn] = xb[(size_t)(c0 + cc) * NN + n0 + nn];
        }
        for (int i = tid; i < 48 * 16; i += 256) {
            int r = i >> 4, cc = i & 15;
            int ch = ch0 + r;
            const float* Wp; int row;
            if (ch < 64)      { Wp = Wq; row = ch; }
            else if (ch < 80) { Wp = Wk; row = ch - 64; }
            else              { Wp = Wv; row = ch - 80; }
            ws[r][cc] = Wp[row * CC + c0 + cc];
        }
        __syncthreads();
        #pragma unroll
        for (int cc = 0; cc < 16; cc++) {
            float4 xr = *reinterpret_cast<const float4*>(&xs[cc][tx * 4]);
            float wr0 = ws[ty * 3 + 0][cc];
            float wr1 = ws[ty * 3 + 1][cc];
            float wr2 = ws[ty * 3 + 2][cc];
            acc[0][0] += wr0 * xr.x; acc[0][1] += wr0 * xr.y; acc[0][2] += wr0 * xr.z; acc[0][3] += wr0 * xr.w;
            acc[1][0] += wr1 * xr.x; acc[1][1] += wr1 * xr.y; acc[1][2] += wr1 * xr.z; acc[1][3] += wr1 * xr.w;
            acc[2][0] += wr2 * xr.x; acc[2][1] += wr2 * xr.y; acc[2][2] += wr2 * xr.z; acc[2][3] += wr2 * xr.w;
        }
        __syncthreads();
    }
    #pragma unroll
    for (int i = 0; i < 3; i++) {
        int ch = ch0 + ty * 3 + i;
        #pragma unroll
        for (int j = 0; j < 4; j++) {
            int n = n0 + tx * 4 + j;
            float val = acc[i][j];
            if (ch < 64)      g_q[(((size_t)b * 64 + ch) << 10) + n] = val;
            else if (ch < 80) g_k[(((size_t)b * 16 + (ch - 64)) << 10) + n] = val;
            else              g_v[(((size_t)b * 64 + (ch - 80)) << 10) + n] = val;
        }
    }
}

// ---------------- K2: BN stats + fused v->fp16 conversion ----------------
__global__ __launch_bounds__(256) void k_bnstats(
    const float* __restrict__ bnw_q, const float* __restrict__ bnb_q,
    const float* __restrict__ bnw_v, const float* __restrict__ bnb_v)
{
    int ch = blockIdx.x;
    int tid = threadIdx.x;
    const float* src = (ch < 64) ? (g_q + (size_t)ch * NN) : (g_v + (size_t)(ch - 64) * NN);
    float s = 0.f, s2 = 0.f;
    for (int i = tid; i < BB * NN; i += 256) {
        int b = i >> 10, n = i & 1023;
        float v = src[((size_t)b * 64 << 10) + n];
        s += v; s2 += v * v;
    }
    __shared__ float rs[256], rs2[256];
    __shared__ float s_sc, s_sh;
    rs[tid] = s; rs2[tid] = s2;
    __syncthreads();
    for (int st = 128; st > 0; st >>= 1) {
        if (tid < st) { rs[tid] += rs[tid + st]; rs2[tid] += rs2[tid + st]; }
        __syncthreads();
    }
    if (tid == 0) {
        float inv = 1.f / (float)(BB * NN);
        float mean = rs[0] * inv;
        float var = rs2[0] * inv - mean * mean;
        float w, bsh;
        if (ch < 64) { w = bnw_q[ch]; bsh = bnb_q[ch]; }
        else         { w = bnw_v[ch - 64]; bsh = bnb_v[ch - 64]; }
        float sc = w * rsqrtf(var + EPSB);
        float sh = bsh - mean * sc;
        if (ch < 64) { g_qs[ch] = sc; g_qb[ch] = sh; }
        else         { g_vs[ch - 64] = sc; g_vb[ch - 64] = sh; }
        s_sc = sc; s_sh = sh;
    }
    __syncthreads();
    if (ch >= 64) {
        // convert this v channel to fp16 (BN folded)
        int v = ch - 64;
        float sc = s_sc, sh = s_sh;
        for (int i = tid; i < BB * NN; i += 256) {
            int b = i >> 10, n = i & 1023;
            float val = src[((size_t)b * 64 << 10) + n];
            g_vh[(((size_t)(b * 64 + v)) << 10) + n] = __float2half(val * sc + sh);
        }
    }
}

// ---------------- K2b: softmax ----------------
__global__ __launch_bounds__(256) void k_softmax()
{
    int row = blockIdx.x;
    float* p = g_k + ((size_t)row << 10);
    int tid = threadIdx.x;
    float v0 = p[tid], v1 = p[tid + 256], v2 = p[tid + 512], v3 = p[tid + 768];
    __shared__ float red[256];
    float mx = fmaxf(fmaxf(v0, v1), fmaxf(v2, v3));
    red[tid] = mx; __syncthreads();
    for (int st = 128; st > 0; st >>= 1) {
        if (tid < st) red[tid] = fmaxf(red[tid], red[tid + st]);
        __syncthreads();
    }
    mx = red[0]; __syncthreads();
    v0 = expf(v0 - mx); v1 = expf(v1 - mx); v2 = expf(v2 - mx); v3 = expf(v3 - mx);
    red[tid] = v0 + v1 + v2 + v3; __syncthreads();
    for (int st = 128; st > 0; st >>= 1) {
        if (tid < st) red[tid] += red[tid + st];
        __syncthreads();
    }
    float inv = 1.f / red[0];
    p[tid] = v0 * inv; p[tid + 256] = v1 * inv; p[tid + 512] = v2 * inv; p[tid + 768] = v3 * inv;
}

// ---------------- K3: lambda_c partials ----------------
__global__ __launch_bounds__(256) void k_lambdac()
{
    int b = blockIdx.x;
    int part = blockIdx.y;
    int nc = part * 128;
    int tid = threadIdx.x;
    int s = tid >> 6, v = tid & 63;
    __shared__ float sbuf[16 * 128 + 128 * 65];
    float* sm_s = sbuf;
    float* vs_s = sbuf + 16 * 128;

    for (int i = tid; i < 16 * 128; i += 256) {
        int k = i >> 7, nn = i & 127;
        sm_s[k * 128 + nn] = g_k[(((size_t)b * 16 + k) << 10) + nc + nn];
    }
    for (int i = tid; i < 64 * 128; i += 256) {
        int vv = i >> 7, nn = i & 127;
        vs_s[nn * 65 + vv] = g_v[(((size_t)b * 64 + vv) << 10) + nc + nn] * g_vs[vv] + g_vb[vv];
    }
    __syncthreads();
    float acc[16] = {};
    for (int nn = s * 32; nn < s * 32 + 32; nn++) {
        float vv = vs_s[nn * 65 + v];
        #pragma unroll
        for (int k = 0; k < 16; k++) acc[k] += sm_s[k * 128 + nn] * vv;
    }
    __syncthreads();
    #pragma unroll
    for (int k = 0; k < 16; k++) sbuf[s * 1024 + k * 64 + v] = acc[k];
    __syncthreads();
    for (int e = tid; e < 1024; e += 256)
        g_lcp[part][b * 1024 + e] = sbuf[e] + sbuf[1024 + e] + sbuf[2048 + e] + sbuf[3072 + e];
}

__global__ __launch_bounds__(256) void k_lcred()
{
    int i = blockIdx.x * 256 + threadIdx.x;
    float s = 0.f;
    #pragma unroll
    for (int p = 0; p < 8; p++) s += g_lcp[p][i];
    g_lc[i] = s;
}

// ---------------- K4: build fp16 Toeplitz matrix T ----------------
__global__ __launch_bounds__(256) void k_buildT(const float* __restrict__ emb)
{
    size_t i = (size_t)blockIdx.x * 256 + threadIdx.x;
    int k = (int)(i >> 19);
    int rem = (int)(i & 0x7FFFF);
    int n = rem >> 9;
    int m0 = (rem & 511) * 2;
    int yn = n >> 5, xn = n & 31;
    float f[2];
    #pragma unroll
    for (int e = 0; e < 2; e++) {
        int mm = m0 + e;
        int dy = (mm >> 5) - yn + 11;
        int dx = (mm & 31) - xn + 11;
        f[e] = ((unsigned)dy < 23u && (unsigned)dx < 23u) ? emb[k * 529 + dy * 23 + dx] : 0.f;
    }
    __half2 h = __floats2half2_rn(f[0], f[1]);
    *reinterpret_cast<__half2*>(g_T + (((size_t)k << 20) + ((size_t)n << 10) + m0)) = h;
}

// ---------------- K5: lambda_p GEMM ----------------
// TC path: 3-stage pipeline, k-group=2 (two D tiles in TMEM), 256 threads.
// Tile: 128 n x 256 bv x (2 k). grid (8 n, 8 bv, 8 kgroup) = 512 CTAs.
// Stage = A(k0) 16KB | A(k1) 16KB | B 32KB = 64KB. 3 stages = 192KB.
#define GEMM_SMEM (1024 + 3 * 65536)

__global__ __launch_bounds__(256) void k_gemm(const float* __restrict__ emb)
{
#if USE_TC
    extern __shared__ char dsm[];
    __shared__ __align__(16) uint64_t s_mbar[3];
    __shared__ uint32_t s_tmem;

    int tid = threadIdx.x;
    int wid = tid >> 5, lane = tid & 31;
    int kg = blockIdx.z;
    int n0 = blockIdx.x * 128;
    int bv0 = blockIdx.y * 256;

    uint32_t raw = smem_u32(dsm);
    uint32_t abase = (raw + 1023) & ~1023u;

    if (wid == 0) {
        TC_ALLOC(smem_u32(&s_tmem), 512);
        TC_RELINQ();
    }
    if (tid == 0) {
        MBAR_INIT(smem_u32(&s_mbar[0]), 1);
        MBAR_INIT(smem_u32(&s_mbar[1]), 1);
        MBAR_INIT(smem_u32(&s_mbar[2]), 1);
    }
    __syncthreads();
    uint32_t tmem = s_tmem;

    const __half* Tk0 = g_T + ((size_t)(2 * kg) << 20);
    const __half* Tk1 = g_T + ((size_t)(2 * kg + 1) << 20);

    // stage s base: abase + s*65536. A0 at +0 (16KB), A1 at +16384, B at +32768 (32KB)
    #define ISSUE_LOADS(chunk, stage) do {                                            \
        int _m0 = (chunk) * 64;                                                       \
        uint32_t _Sb = abase + (stage) * 65536;                                       \
        for (int _i = tid; _i < 1024; _i += 256) {                                    \
            int _r = _i >> 3, _c = _i & 7;                                            \
            uint32_t _o = _r * 128 + _c * 16;                                         \
            uint32_t _s = _o ^ ((_o >> 3) & 0x70);                                    \
            cpasync16(_Sb + _s, Tk0 + (((size_t)(n0 + _r) << 10) + _m0 + _c * 8));    \
        }                                                                             \
        for (int _i = tid; _i < 1024; _i += 256) {                                    \
            int _r = _i >> 3, _c = _i & 7;                                            \
            uint32_t _o = _r * 128 + _c * 16;                                         \
            uint32_t _s = _o ^ ((_o >> 3) & 0x70);                                    \
            cpasync16(_Sb + 16384 + _s, Tk1 + (((size_t)(n0 + _r) << 10) + _m0 + _c * 8)); \
        }                                                                             \
        for (int _i = tid; _i < 2048; _i += 256) {                                    \
            int _r = _i >> 3, _c = _i & 7;                                            \
            uint32_t _o = _r * 128 + _c * 16;                                         \
            uint32_t _s = _o ^ ((_o >> 3) & 0x70);                                    \
            cpasync16(_Sb + 32768 + _s, g_vh + (((size_t)(bv0 + _r) << 10) + _m0 + _c * 8)); \
        }                                                                             \
    } while (0)

    ISSUE_LOADS(0, 0); CP_COMMIT();
    ISSUE_LOADS(1, 1); CP_COMMIT();
    ISSUE_LOADS(2, 2); CP_COMMIT();

    const uint32_t idesc = (1u << 4) | (32u << 17) | (8u << 24);  // F32 acc, f16, N=256, M=128
    uint32_t ph0 = 0, ph1 = 0, ph2 = 0;

    for (int c = 0; c < 16; c++) {
        int s = c - (c / 3) * 3;
        if (c < 14)       CP_WAIT(2);
        else if (c == 14) CP_WAIT(1);
        else              CP_WAIT(0);
        __syncthreads();
        if (wid == 0) {
            FENCE_ASYNC();
            if (elect1()) {
                uint32_t sb = abase + s * 65536;
                uint64_t a0 = mk_desc(sb);
                uint64_t a1 = mk_desc(sb + 16384);
                uint64_t bd = mk_desc(sb + 32768);
                #pragma unroll
                for (int ks = 0; ks < 4; ks++) {
                    uint32_t en = (c | ks) != 0;
                    mma_f16_ss(tmem,       a0 + ks * 2, bd + ks * 2, idesc, en);
                    mma_f16_ss(tmem + 256, a1 + ks * 2, bd + ks * 2, idesc, en);
                }
                TC_COMMIT(smem_u32(&s_mbar[s]));
            }
        }
        if (c + 3 < 16) {
            uint32_t ph = (s == 0) ? ph0 : (s == 1) ? ph1 : ph2;
            MBAR_WAIT(smem_u32(&s_mbar[s]), ph);
            if (s == 0) ph0 ^= 1; else if (s == 1) ph1 ^= 1; else ph2 ^= 1;
            ISSUE_LOADS(c + 3, s);
            CP_COMMIT();
        }
    }
    // drain remaining MMA completions: chunks 13 (mbar1), 14 (mbar2), 15 (mbar0)
    MBAR_WAIT(smem_u32(&s_mbar[1]), ph1);
    MBAR_WAIT(smem_u32(&s_mbar[2]), ph2);
    MBAR_WAIT(smem_u32(&s_mbar[0]), ph0);
    TC_FENCE_AFTER();

    // epilogue: two D tiles (128n x 256bv fp32) -> g_lph fp16 [b][k][n][v]
    int t = wid >> 2;                       // which D tile (k within group)
    int kk = 2 * kg + t;
    int n_g = n0 + (wid & 3) * 32 + lane;
    for (int c0 = 0; c0 < 256; c0 += 32) {
        uint32_t r[32];
        TC_LD_X32(r, tmem + t * 256 + c0);
        TC_WAIT_LD();
        int bvb = bv0 + c0;
        int b = bvb >> 6, vb = bvb & 63;
        uint32_t h2[16];
        #pragma unroll
        for (int j = 0; j < 16; j++) {
            __half2 h = __floats2half2_rn(__uint_as_float(r[2 * j]), __uint_as_float(r[2 * j + 1]));
            h2[j] = *reinterpret_cast<uint32_t*>(&h);
        }
        __half* dst = g_lph + ((((size_t)(b * 16 + kk) << 10) + n_g) << 6) + vb;
        uint4* d4 = reinterpret_cast<uint4*>(dst);
        #pragma unroll
        for (int q4 = 0; q4 < 4; q4++)
            d4[q4] = make_uint4(h2[4 * q4], h2[4 * q4 + 1], h2[4 * q4 + 2], h2[4 * q4 + 3]);
    }
    __syncthreads();
    if (tid == 0) {
        MBAR_INVAL(smem_u32(&s_mbar[0]));
        MBAR_INVAL(smem_u32(&s_mbar[1]));
        MBAR_INVAL(smem_u32(&s_mbar[2]));
    }
    __syncthreads();
    if (wid == 0) TC_DEALLOC(tmem, 512);
    #undef ISSUE_LOADS

#else  // ---- fallback: scalar direct conv (correct on any target) ----
    extern __shared__ char dsm[];
    float* img = (float*)dsm;            // 54*55
    float* Es  = img + 54 * 55;          // 16*529
    int tid = threadIdx.x;
    int bid = blockIdx.x + blockIdx.y * 8 + blockIdx.z * 64;  // 0..511

    for (int i = tid; i < 16 * 529; i += 256) Es[i] = emb[i];

    for (int pair = 0; pair < 4; pair++) {
        int bv = bid * 4 + pair;
        int b = bv >> 6, v = bv & 63;
        __syncthreads();
        for (int i = tid; i < 54 * 55; i += 256) img[i] = 0.f;
        __syncthreads();
        float vsc = g_vs[v], vsh = g_vb[v];
        const float* src = g_v + ((size_t)bv << 10);
        for (int i = tid; i < 1024; i += 256) {
            int y = i >> 5, x = i & 31;
            img[(y + PADL) * 55 + x + PADL] = src[i] * vsc + vsh;
        }
        __syncthreads();

        for (int it = 0; it < 4; it++) {
            int task = tid + 256 * it;
            int k = task >> 6;
            int rh = task & 63;
            int row = rh >> 1;
            int xb = (rh & 1) << 4;
            float acc[16] = {};
            const float* ek = Es + k * 529;
            #pragma unroll 1
            for (int i = 0; i < RR; i++) {
                const float* rp = img + (row + i) * 55 + xb;
                float r[38];
                #pragma unroll
                for (int tt = 0; tt < 38; tt++) r[tt] = rp[tt];
                const float* ept = ek + i * RR;
                #pragma unroll
                for (int j = 0; j < RR; j++) {
                    float e = ept[j];
                    #pragma unroll
                    for (int x = 0; x < 16; x++) acc[x] += e * r[j + x];
                }
            }
            int nbase = row * 32 + xb;
            __half* o = g_lph + ((((size_t)(b * 16 + k) << 10) + nbase) << 6) + v;
            #pragma unroll
            for (int x = 0; x < 16; x++) o[(size_t)x << 6] = __float2half(acc[x]);
        }
    }
#endif
}

// ---------------- K6: final contraction ----------------
// grid (4 nchunks, 4 vgroups, 32 b), 256 threads; thread = one n position.
__global__ __launch_bounds__(256) void k_final(const float* __restrict__ gamma,
                                               float* __restrict__ out)
{
    int b = blockIdx.z;
    int v0 = blockIdx.y * 16;
    int n = blockIdx.x * 256 + threadIdx.x;
    __shared__ float lc_s[256];            // [k][vgroup 16]
    for (int i = threadIdx.x; i < 256; i += 256)
        lc_s[i] = g_lc[b * 1024 + (i >> 4) * 64 + v0 + (i & 15)];
    __syncthreads();
    float qv[64];
    #pragma unroll
    for (int ch = 0; ch < 64; ch++)
        qv[ch] = g_q[(((size_t)b * 64 + ch) << 10) + n] * g_qs[ch] + g_qb[ch];
    float gm = 1.f + gamma[0];
    float y[4][16] = {};
    for (int k = 0; k < 16; k++) {
        const __half2* lp = reinterpret_cast<const __half2*>(
            g_lph + ((((size_t)(b * 16 + k) << 10) + n) << 6) + v0);
        float lam[16];
        #pragma unroll
        for (int j = 0; j < 8; j++) {
            float2 f = __half22float2(lp[j]);
            lam[2 * j] = f.x; lam[2 * j + 1] = f.y;
        }
        #pragma unroll
        for (int jj = 0; jj < 16; jj++) lam[jj] += lc_s[k * 16 + jj];
        #pragma unroll
        for (int h = 0; h < 4; h++) {
            float qh = qv[h * 16 + k];
            #pragma unroll
            for (int jj = 0; jj < 16; jj++) y[h][jj] += qh * lam[jj];
        }
    }
    #pragma unroll
    for (int h = 0; h < 4; h++)
        #pragma unroll
        for (int jj = 0; jj < 16; jj++)
            out[(((size_t)b * 256) + h * 64 + v0 + jj) * NN + n] = y[h][jj] * gm;
}

// ---------------- launch ----------------
extern "C" void kernel_launch(void* const* d_in, const int* in_sizes, int n_in,
                              void* d_out, int out_size)
{
    const float* x      = (const float*)d_in[0];
    const float* Wq     = (const float*)d_in[1];
    const float* bn_q_w = (const float*)d_in[2];
    const float* bn_q_b = (const float*)d_in[3];
    const float* Wk     = (const float*)d_in[4];
    const float* Wv     = (const float*)d_in[5];
    const float* bn_v_w = (const float*)d_in[6];
    const float* bn_v_b = (const float*)d_in[7];
    const float* emb    = (const float*)d_in[8];
    const float* gamma  = (const float*)d_in[9];
    float* out = (float*)d_out;

    cudaFuncSetAttribute(k_gemm, cudaFuncAttributeMaxDynamicSharedMemorySize, GEMM_SMEM);

    k_buildT<<<32768, 256>>>(emb);                          // 1
    k_project<<<dim3(16, 3, 32), 256>>>(x, Wq, Wk, Wv);     // 2
    k_bnstats<<<128, 256>>>(bn_q_w, bn_q_b, bn_v_w, bn_v_b);// 3 (fused vhalf)
    k_gemm<<<dim3(8, 8, 8), 256, GEMM_SMEM>>>(emb);         // 4  <-- ncu samples this slot
    k_softmax<<<512, 256>>>();                              // 5
    k_lambdac<<<dim3(32, 8), 256>>>();                      // 6
    k_lcred<<<128, 256>>>();                                // 7
    k_final<<<dim3(4, 4, 32), 256>>>(gamma, out);           // 8
}

// round 6
// speedup vs baseline: 3.7372x; 1.4641x over previous
#include <cuda_runtime.h>
#include <cuda_fp16.h>
#include <cstdint>
#include <math.h>

#define BB 32
#define CC 256
#define NN 1024
#define QCH 64
#define KCH 16
#define VCH 64
#define HEADS 4
#define KD 16
#define RR 23
#define PADL 11
#define EPSB 1e-5f

// arch-specific (tcgen05-capable) compilation pass?
#if defined(__CUDA_ARCH_FEAT_SM103_ALL) || defined(__CUDA_ARCH_FEAT_SM100_ALL) || \
    defined(__CUDA_ARCH_FEAT_SM101_ALL) || defined(__CUDA_ARCH_SPECIFIC__) || \
    defined(__CUDA_ARCH_FAMILY_SPECIFIC__)
#define USE_TC 1
#else
#define USE_TC 0
#endif

// ---------------- scratch ----------------
__device__ float g_q[BB * QCH * NN];
__device__ float g_k[BB * KCH * NN];
__device__ float g_v[BB * VCH * NN];
__device__ __half g_lph[(size_t)BB * KD * NN * VCH];   // lambda_p fp16 [b][k][n][v]
__device__ float g_lc[BB * KD * VCH];
__device__ float g_lcp[8][BB * KD * VCH];
__device__ float g_qs[QCH], g_qb[QCH];
__device__ float g_vs[VCH], g_vb[VCH];
__device__ __half g_T[(size_t)16 * 1024 * 1024];       // Toeplitz conv matrix fp16, 32MB
__device__ __half g_vh[(size_t)2048 * 1024];           // BN'd v fp16 [bv][m]
__device__ __half g_xh[(size_t)BB * NN * CC];          // x fp16 transposed [b][n][c], 16MB
__device__ __half g_wh[160 * 256];                     // W fp16 [160 ch pad][256 c]

// ---------------- PTX helpers ----------------
__device__ __forceinline__ uint32_t smem_u32(const void* p) {
    uint32_t r;
    asm("{ .reg .u64 t; cvta.to.shared.u64 t, %1; cvt.u32.u64 %0, t; }" : "=r"(r) : "l"(p));
    return r;
}
__device__ __forceinline__ void cpasync16(uint32_t s, const void* g) {
    asm volatile("cp.async.cg.shared.global [%0], [%1], 16;" :: "r"(s), "l"(g));
}
#define CP_COMMIT()  asm volatile("cp.async.commit_group;" ::: "memory")
#define CP_WAIT(n)   asm volatile("cp.async.wait_group %0;" :: "n"(n) : "memory")

#if USE_TC
__device__ __forceinline__ uint32_t elect1() {
    uint32_t p;
    asm volatile("{ .reg .pred p; elect.sync _|p, 0xFFFFFFFF; selp.b32 %0,1,0,p; }" : "=r"(p));
    return p;
}
#define MBAR_INIT(a, c) asm volatile("mbarrier.init.shared.b64 [%0], %1;" :: "r"(a), "r"(c) : "memory")
#define MBAR_INVAL(a)   asm volatile("mbarrier.inval.shared.b64 [%0];" :: "r"(a) : "memory")
#define MBAR_WAIT(a, ph) do { \
    uint32_t _m = (a), _p = (ph), _d; \
    asm volatile("{ .reg .pred p; mbarrier.try_wait.parity.acquire.cta.shared::cta.b64 p, [%1], %2; selp.b32 %0,1,0,p; }" \
        : "=r"(_d) : "r"(_m), "r"(_p) : "memory"); \
    if (!_d) { \
        asm volatile("{ .reg .pred P1; WL_%=: mbarrier.try_wait.parity.acquire.cta.shared::cta.b64 P1, [%0], %1, 0x989680; @P1 bra.uni WD_%=; bra.uni WL_%=; WD_%=: }" \
            :: "r"(_m), "r"(_p) : "memory"); \
    } } while (0)

#define TC_ALLOC(sa, n)   asm volatile("tcgen05.alloc.cta_group::1.sync.aligned.shared::cta.b32 [%0], %1;" :: "r"(sa), "r"(n) : "memory")
#define TC_DEALLOC(t, n)  asm volatile("tcgen05.dealloc.cta_group::1.sync.aligned.b32 %0, %1;" :: "r"(t), "r"(n))
#define TC_RELINQ()       asm volatile("tcgen05.relinquish_alloc_permit.cta_group::1.sync.aligned;")
#define TC_COMMIT(mb)     asm volatile("tcgen05.commit.cta_group::1.mbarrier::arrive::one.shared::cluster.b64 [%0];" :: "r"(mb) : "memory")
#define TC_FENCE_AFTER()  asm volatile("tcgen05.fence::after_thread_sync;" ::: "memory")
#define TC_WAIT_LD()      asm volatile("tcgen05.wait::ld.sync.aligned;" ::: "memory")
#define FENCE_ASYNC()     asm volatile("fence.proxy.async.shared::cta;" ::: "memory")

#define TC_LD_X32(r, t) \
    asm volatile("tcgen05.ld.sync.aligned.32x32b.x32.b32 " \
        "{%0,%1,%2,%3,%4,%5,%6,%7,%8,%9,%10,%11,%12,%13,%14,%15," \
        "%16,%17,%18,%19,%20,%21,%22,%23,%24,%25,%26,%27,%28,%29,%30,%31}, [%32];" \
        : "=r"((r)[0]),"=r"((r)[1]),"=r"((r)[2]),"=r"((r)[3]),"=r"((r)[4]),"=r"((r)[5]),"=r"((r)[6]),"=r"((r)[7]), \
          "=r"((r)[8]),"=r"((r)[9]),"=r"((r)[10]),"=r"((r)[11]),"=r"((r)[12]),"=r"((r)[13]),"=r"((r)[14]),"=r"((r)[15]), \
          "=r"((r)[16]),"=r"((r)[17]),"=r"((r)[18]),"=r"((r)[19]),"=r"((r)[20]),"=r"((r)[21]),"=r"((r)[22]),"=r"((r)[23]), \
          "=r"((r)[24]),"=r"((r)[25]),"=r"((r)[26]),"=r"((r)[27]),"=r"((r)[28]),"=r"((r)[29]),"=r"((r)[30]),"=r"((r)[31]) \
        : "r"(t))

__device__ __forceinline__ void mma_f16_ss(uint32_t d, uint64_t ad, uint64_t bd,
                                           uint32_t idesc, uint32_t en) {
    asm volatile(
        "{ .reg .pred p; setp.ne.u32 p, %4, 0;\n\t"
        "tcgen05.mma.cta_group::1.kind::f16 [%0], %1, %2, %3, {%5,%5,%5,%5}, p;\n\t}"
        :: "r"(d), "l"(ad), "l"(bd), "r"(idesc), "r"(en), "r"(0u) : "memory");
}

static constexpr uint64_t DESC_BASE =
    (uint64_t(2) << 61) | (uint64_t(1) << 46) | (uint64_t(64) << 32) | (uint64_t(1) << 16);
__device__ __forceinline__ uint64_t mk_desc(uint32_t a) {
    return DESC_BASE | ((uint64_t)(a >> 4) & 0x3FFF);
}
#endif // USE_TC

// ---------------- K0a: x fp32 -> fp16 transposed [b][n][c] ----------------
__global__ __launch_bounds__(256) void k_xhalf(const float* __restrict__ x)
{
    int b = blockIdx.z, ct = blockIdx.y, nt = blockIdx.x;
    int n0 = nt * 64, c0 = ct * 64;
    __shared__ float s[64][65];
    int tid = threadIdx.x;
    for (int i = tid; i < 64 * 64; i += 256) {
        int c = i >> 6, n = i & 63;
        s[c][n] = x[((size_t)b * 256 + c0 + c) * 1024 + n0 + n];
    }
    __syncthreads();
    for (int i = tid; i < 64 * 32; i += 256) {
        int n = i >> 5, c2 = (i & 31) * 2;
        __half2 h = __floats2half2_rn(s[c2][n], s[c2 + 1][n]);
        *reinterpret_cast<__half2*>(&g_xh[((size_t)b * 1024 + n0 + n) * 256 + c0 + c2]) = h;
    }
}

// ---------------- K0b: pack W (q|k|v) into fp16 [160][256], zero pad ----------------
__global__ __launch_bounds__(256) void k_whalf(
    const float* __restrict__ Wq, const float* __restrict__ Wk, const float* __restrict__ Wv)
{
    int i = blockIdx.x * 256 + threadIdx.x;   // 160*256 = 40960
    int row = i >> 8, c = i & 255;
    float val;
    if (row < 64)       val = Wq[row * 256 + c];
    else if (row < 80)  val = Wk[(row - 64) * 256 + c];
    else if (row < 144) val = Wv[(row - 80) * 256 + c];
    else                val = 0.f;
    g_wh[i] = __float2half(val);
}

// ---------------- K1: projections via tcgen05 (M=128 n, N=160 ch, K=256) -----
// grid (8 ntiles, 32 b), 128 threads. smem: A 4x16KB chunks + B 4x20KB chunks.
#define PROJ_SMEM (1024 + 4 * 16384 + 4 * 20480)

__global__ __launch_bounds__(128) void k_proj()
{
#if USE_TC
    extern __shared__ char dsm[];
    __shared__ __align__(16) uint64_t s_mbar;
    __shared__ uint32_t s_tmem;
    int tid = threadIdx.x;
    int wid = tid >> 5, lane = tid & 31;
    int b = blockIdx.y;
    int n0 = blockIdx.x * 128;

    uint32_t raw = smem_u32(dsm);
    uint32_t Ab = (raw + 1023) & ~1023u;
    uint32_t Bb = Ab + 4 * 16384;

    if (wid == 0) { TC_ALLOC(smem_u32(&s_tmem), 256); TC_RELINQ(); }
    if (tid == 0) MBAR_INIT(smem_u32(&s_mbar), 1);
    __syncthreads();
    uint32_t tmem = s_tmem;

    // A: xh rows n0..n0+127, 4 K-chunks of 64 c (128B rows, SW128)
    for (int i = tid; i < 4096; i += 128) {
        int ch = i >> 10, r = (i >> 3) & 127, col = i & 7;
        uint32_t o = r * 128 + col * 16;
        uint32_t sw = o ^ ((o >> 3) & 0x70);
        cpasync16(Ab + ch * 16384 + sw,
                  g_xh + (((size_t)b * 1024 + n0 + r) << 8) + ch * 64 + col * 8);
    }
    // B: W 160 rows, 4 K-chunks
    for (int i = tid; i < 5120; i += 128) {
        int ch = i >> 10 >= 4 ? 0 : 0, dummy = 0; (void)dummy;
        int idx = i;
        int chb = idx / 1280, rem = idx % 1280;
        int r = rem >> 3, col = rem & 7;
        uint32_t o = r * 128 + col * 16;
        uint32_t sw = o ^ ((o >> 3) & 0x70);
        cpasync16(Bb + chb * 20480 + sw, g_wh + r * 256 + chb * 64 + col * 8);
        (void)ch;
    }
    CP_COMMIT();
    CP_WAIT(0);
    __syncthreads();

    const uint32_t idesc = (1u << 4) | (20u << 17) | (8u << 24);  // F32 acc, f16, N=160, M=128
    if (wid == 0) {
        FENCE_ASYNC();
        if (elect1()) {
            #pragma unroll
            for (int c = 0; c < 4; c++) {
                uint64_t ad = mk_desc(Ab + c * 16384);
                uint64_t bd = mk_desc(Bb + c * 20480);
                #pragma unroll
                for (int ks = 0; ks < 4; ks++)
                    mma_f16_ss(tmem, ad + ks * 2, bd + ks * 2, idesc, (c | ks) != 0);
            }
            TC_COMMIT(smem_u32(&s_mbar));
        }
    }
    MBAR_WAIT(smem_u32(&s_mbar), 0);
    TC_FENCE_AFTER();

    int n_g = n0 + wid * 32 + lane;
    for (int c0 = 0; c0 < 160; c0 += 32) {
        uint32_t r[32];
        TC_LD_X32(r, tmem + c0);
        TC_WAIT_LD();
        #pragma unroll
        for (int j = 0; j < 32; j++) {
            int ch = c0 + j;
            float val = __uint_as_float(r[j]);
            if (ch < 64)       g_q[(((size_t)b * 64 + ch) << 10) + n_g] = val;
            else if (ch < 80)  g_k[(((size_t)b * 16 + (ch - 64)) << 10) + n_g] = val;
            else if (ch < 144) g_v[(((size_t)b * 64 + (ch - 80)) << 10) + n_g] = val;
        }
    }
    __syncthreads();
    if (tid == 0) MBAR_INVAL(smem_u32(&s_mbar));
    __syncthreads();
    if (wid == 0) TC_DEALLOC(tmem, 256);
#else
    // fallback scalar projection (never selected on sm_103a hardware)
    int b = blockIdx.y;
    int n = blockIdx.x * 128 + threadIdx.x;
    const __half* xr = g_xh + (((size_t)b * 1024 + n) << 8);
    for (int ch = 0; ch < 144; ch++) {
        float acc = 0.f;
        for (int c = 0; c < 256; c++)
            acc += __half2float(g_wh[ch * 256 + c]) * __half2float(xr[c]);
        if (ch < 64)       g_q[(((size_t)b * 64 + ch) << 10) + n] = acc;
        else if (ch < 80)  g_k[(((size_t)b * 16 + (ch - 64)) << 10) + n] = acc;
        else               g_v[(((size_t)b * 64 + (ch - 80)) << 10) + n] = acc;
    }
#endif
}

// ---------------- K2: BN stats + fused v->fp16 conversion ----------------
__global__ __launch_bounds__(256) void k_bnstats(
    const float* __restrict__ bnw_q, const float* __restrict__ bnb_q,
    const float* __restrict__ bnw_v, const float* __restrict__ bnb_v)
{
    int ch = blockIdx.x;
    int tid = threadIdx.x;
    const float* src = (ch < 64) ? (g_q + (size_t)ch * NN) : (g_v + (size_t)(ch - 64) * NN);
    float s = 0.f, s2 = 0.f;
    for (int i = tid; i < BB * NN; i += 256) {
        int b = i >> 10, n = i & 1023;
        float v = src[((size_t)b * 64 << 10) + n];
        s += v; s2 += v * v;
    }
    __shared__ float rs[256], rs2[256];
    __shared__ float s_sc, s_sh;
    rs[tid] = s; rs2[tid] = s2;
    __syncthreads();
    for (int st = 128; st > 0; st >>= 1) {
        if (tid < st) { rs[tid] += rs[tid + st]; rs2[tid] += rs2[tid + st]; }
        __syncthreads();
    }
    if (tid == 0) {
        float inv = 1.f / (float)(BB * NN);
        float mean = rs[0] * inv;
        float var = rs2[0] * inv - mean * mean;
        float w, bsh;
        if (ch < 64) { w = bnw_q[ch]; bsh = bnb_q[ch]; }
        else         { w = bnw_v[ch - 64]; bsh = bnb_v[ch - 64]; }
        float sc = w * rsqrtf(var + EPSB);
        float sh = bsh - mean * sc;
        if (ch < 64) { g_qs[ch] = sc; g_qb[ch] = sh; }
        else         { g_vs[ch - 64] = sc; g_vb[ch - 64] = sh; }
        s_sc = sc; s_sh = sh;
    }
    __syncthreads();
    if (ch >= 64) {
        int v = ch - 64;
        float sc = s_sc, sh = s_sh;
        for (int i = tid; i < BB * NN; i += 256) {
            int b = i >> 10, n = i & 1023;
            float val = src[((size_t)b * 64 << 10) + n];
            g_vh[(((size_t)(b * 64 + v)) << 10) + n] = __float2half(val * sc + sh);
        }
    }
}

// ---------------- K2b: softmax ----------------
__global__ __launch_bounds__(256) void k_softmax()
{
    int row = blockIdx.x;
    float* p = g_k + ((size_t)row << 10);
    int tid = threadIdx.x;
    float v0 = p[tid], v1 = p[tid + 256], v2 = p[tid + 512], v3 = p[tid + 768];
    __shared__ float red[256];
    float mx = fmaxf(fmaxf(v0, v1), fmaxf(v2, v3));
    red[tid] = mx; __syncthreads();
    for (int st = 128; st > 0; st >>= 1) {
        if (tid < st) red[tid] = fmaxf(red[tid], red[tid + st]);
        __syncthreads();
    }
    mx = red[0]; __syncthreads();
    v0 = expf(v0 - mx); v1 = expf(v1 - mx); v2 = expf(v2 - mx); v3 = expf(v3 - mx);
    red[tid] = v0 + v1 + v2 + v3; __syncthreads();
    for (int st = 128; st > 0; st >>= 1) {
        if (tid < st) red[tid] += red[tid + st];
        __syncthreads();
    }
    float inv = 1.f / red[0];
    p[tid] = v0 * inv; p[tid + 256] = v1 * inv; p[tid + 512] = v2 * inv; p[tid + 768] = v3 * inv;
}

// ---------------- K3: lambda_c partials (reads BN'd fp16 v) ----------------
__global__ __launch_bounds__(256) void k_lambdac()
{
    int b = blockIdx.x;
    int part = blockIdx.y;
    int nc = part * 128;
    int tid = threadIdx.x;
    int s = tid >> 6, v = tid & 63;
    __shared__ float sbuf[16 * 128 + 128 * 65];
    float* sm_s = sbuf;
    float* vs_s = sbuf + 16 * 128;

    for (int i = tid; i < 16 * 128; i += 256) {
        int k = i >> 7, nn = i & 127;
        sm_s[k * 128 + nn] = g_k[(((size_t)b * 16 + k) << 10) + nc + nn];
    }
    for (int i = tid; i < 64 * 128; i += 256) {
        int vv = i >> 7, nn = i & 127;
        vs_s[nn * 65 + vv] = __half2float(g_vh[(((size_t)b * 64 + vv) << 10) + nc + nn]);
    }
    __syncthreads();
    float acc[16] = {};
    for (int nn = s * 32; nn < s * 32 + 32; nn++) {
        float vv = vs_s[nn * 65 + v];
        #pragma unroll
        for (int k = 0; k < 16; k++) acc[k] += sm_s[k * 128 + nn] * vv;
    }
    __syncthreads();
    #pragma unroll
    for (int k = 0; k < 16; k++) sbuf[s * 1024 + k * 64 + v] = acc[k];
    __syncthreads();
    for (int e = tid; e < 1024; e += 256)
        g_lcp[part][b * 1024 + e] = sbuf[e] + sbuf[1024 + e] + sbuf[2048 + e] + sbuf[3072 + e];
}

__global__ __launch_bounds__(256) void k_lcred()
{
    int i = blockIdx.x * 256 + threadIdx.x;
    float s = 0.f;
    #pragma unroll
    for (int p = 0; p < 8; p++) s += g_lcp[p][i];
    g_lc[i] = s;
}

// ---------------- K4: build fp16 Toeplitz matrix T ----------------
__global__ __launch_bounds__(256) void k_buildT(const float* __restrict__ emb)
{
    size_t i = (size_t)blockIdx.x * 256 + threadIdx.x;
    int k = (int)(i >> 19);
    int rem = (int)(i & 0x7FFFF);
    int n = rem >> 9;
    int m0 = (rem & 511) * 2;
    int yn = n >> 5, xn = n & 31;
    float f[2];
    #pragma unroll
    for (int e = 0; e < 2; e++) {
        int mm = m0 + e;
        int dy = (mm >> 5) - yn + 11;
        int dx = (mm & 31) - xn + 11;
        f[e] = ((unsigned)dy < 23u && (unsigned)dx < 23u) ? emb[k * 529 + dy * 23 + dx] : 0.f;
    }
    __half2 h = __floats2half2_rn(f[0], f[1]);
    *reinterpret_cast<__half2*>(g_T + (((size_t)k << 20) + ((size_t)n << 10) + m0)) = h;
}

// ---------------- K5: lambda_p GEMM (zero-chunk skipping) ----------------
// 3-stage pipeline, k-group=2, 256 threads. Tile 128n x 256bv.
// Only m-chunks with |y_m - y_n| <= 11 are nonzero: 8..14 of 16 chunks.
#define GEMM_SMEM (1024 + 3 * 65536)

__global__ __launch_bounds__(256) void k_gemm(const float* __restrict__ emb)
{
#if USE_TC
    extern __shared__ char dsm[];
    __shared__ __align__(16) uint64_t s_mbar[3];
    __shared__ uint32_t s_tmem;

    int tid = threadIdx.x;
    int wid = tid >> 5, lane = tid & 31;
    int kg = blockIdx.z;
    int n0 = blockIdx.x * 128;
    int bv0 = blockIdx.y * 256;

    int y0 = blockIdx.x * 4;
    int c_lo = (y0 > 11) ? ((y0 - 11) >> 1) : 0;
    int c_hi = min(15, (y0 + 14) >> 1);
    int nch = c_hi - c_lo + 1;

    uint32_t raw = smem_u32(dsm);
    uint32_t abase = (raw + 1023) & ~1023u;

    if (wid == 0) { TC_ALLOC(smem_u32(&s_tmem), 512); TC_RELINQ(); }
    if (tid == 0) {
        MBAR_INIT(smem_u32(&s_mbar[0]), 1);
        MBAR_INIT(smem_u32(&s_mbar[1]), 1);
        MBAR_INIT(smem_u32(&s_mbar[2]), 1);
    }
    __syncthreads();
    uint32_t tmem = s_tmem;

    const __half* Tk0 = g_T + ((size_t)(2 * kg) << 20);
    const __half* Tk1 = g_T + ((size_t)(2 * kg + 1) << 20);

    #define ISSUE_LOADS(chunk, stage) do {                                            \
        int _m0 = (chunk) * 64;                                                       \
        uint32_t _Sb = abase + (stage) * 65536;                                       \
        for (int _i = tid; _i < 1024; _i += 256) {                                    \
            int _r = _i >> 3, _c = _i & 7;                                            \
            uint32_t _o = _r * 128 + _c * 16;                                         \
            uint32_t _s = _o ^ ((_o >> 3) & 0x70);                                    \
            cpasync16(_Sb + _s, Tk0 + (((size_t)(n0 + _r) << 10) + _m0 + _c * 8));    \
        }                                                                             \
        for (int _i = tid; _i < 1024; _i += 256) {                                    \
            int _r = _i >> 3, _c = _i & 7;                                            \
            uint32_t _o = _r * 128 + _c * 16;                                         \
            uint32_t _s = _o ^ ((_o >> 3) & 0x70);                                    \
            cpasync16(_Sb + 16384 + _s, Tk1 + (((size_t)(n0 + _r) << 10) + _m0 + _c * 8)); \
        }                                                                             \
        for (int _i = tid; _i < 2048; _i += 256) {                                    \
            int _r = _i >> 3, _c = _i & 7;                                            \
            uint32_t _o = _r * 128 + _c * 16;                                         \
            uint32_t _s = _o ^ ((_o >> 3) & 0x70);                                    \
            cpasync16(_Sb + 32768 + _s, g_vh + (((size_t)(bv0 + _r) << 10) + _m0 + _c * 8)); \
        }                                                                             \
    } while (0)

    ISSUE_LOADS(c_lo + 0, 0); CP_COMMIT();
    ISSUE_LOADS(c_lo + 1, 1); CP_COMMIT();
    ISSUE_LOADS(c_lo + 2, 2); CP_COMMIT();

    const uint32_t idesc = (1u << 4) | (32u << 17) | (8u << 24);  // F32 acc, f16, N=256, M=128
    uint32_t ph0 = 0, ph1 = 0, ph2 = 0;

    for (int ci = 0; ci < nch; ci++) {
        int s = ci - (ci / 3) * 3;
        if (ci <= nch - 3)      CP_WAIT(2);
        else if (ci == nch - 2) CP_WAIT(1);
        else                    CP_WAIT(0);
        __syncthreads();
        if (wid == 0) {
            FENCE_ASYNC();
            if (elect1()) {
                uint32_t sb = abase + s * 65536;
                uint64_t a0 = mk_desc(sb);
                uint64_t a1 = mk_desc(sb + 16384);
                uint64_t bd = mk_desc(sb + 32768);
                #pragma unroll
                for (int ks = 0; ks < 4; ks++) {
                    uint32_t en = (ci | ks) != 0;
                    mma_f16_ss(tmem,       a0 + ks * 2, bd + ks * 2, idesc, en);
                    mma_f16_ss(tmem + 256, a1 + ks * 2, bd + ks * 2, idesc, en);
                }
                TC_COMMIT(smem_u32(&s_mbar[s]));
            }
        }
        if (ci + 3 < nch) {
            uint32_t ph = (s == 0) ? ph0 : (s == 1) ? ph1 : ph2;
            MBAR_WAIT(smem_u32(&s_mbar[s]), ph);
            if (s == 0) ph0 ^= 1; else if (s == 1) ph1 ^= 1; else ph2 ^= 1;
            ISSUE_LOADS(c_lo + ci + 3, s);
            CP_COMMIT();
        }
    }
    // drain the three outstanding MMA commits (one per stage)
    MBAR_WAIT(smem_u32(&s_mbar[0]), ph0);
    MBAR_WAIT(smem_u32(&s_mbar[1]), ph1);
    MBAR_WAIT(smem_u32(&s_mbar[2]), ph2);
    TC_FENCE_AFTER();

    // epilogue: two D tiles (128n x 256bv fp32) -> g_lph fp16 [b][k][n][v]
    int t = wid >> 2;
    int kk = 2 * kg + t;
    int n_g = n0 + (wid & 3) * 32 + lane;
    for (int c0 = 0; c0 < 256; c0 += 32) {
        uint32_t r[32];
        TC_LD_X32(r, tmem + t * 256 + c0);
        TC_WAIT_LD();
        int bvb = bv0 + c0;
        int b = bvb >> 6, vb = bvb & 63;
        uint32_t h2[16];
        #pragma unroll
        for (int j = 0; j < 16; j++) {
            __half2 h = __floats2half2_rn(__uint_as_float(r[2 * j]), __uint_as_float(r[2 * j + 1]));
            h2[j] = *reinterpret_cast<uint32_t*>(&h);
        }
        __half* dst = g_lph + ((((size_t)(b * 16 + kk) << 10) + n_g) << 6) + vb;
        uint4* d4 = reinterpret_cast<uint4*>(dst);
        #pragma unroll
        for (int q4 = 0; q4 < 4; q4++)
            d4[q4] = make_uint4(h2[4 * q4], h2[4 * q4 + 1], h2[4 * q4 + 2], h2[4 * q4 + 3]);
    }
    __syncthreads();
    if (tid == 0) {
        MBAR_INVAL(smem_u32(&s_mbar[0]));
        MBAR_INVAL(smem_u32(&s_mbar[1]));
        MBAR_INVAL(smem_u32(&s_mbar[2]));
    }
    __syncthreads();
    if (wid == 0) TC_DEALLOC(tmem, 512);
    #undef ISSUE_LOADS

#else  // ---- fallback: scalar direct conv ----
    extern __shared__ char dsm[];
    float* img = (float*)dsm;
    float* Es  = img + 54 * 55;
    int tid = threadIdx.x;
    int bid = blockIdx.x + blockIdx.y * 8 + blockIdx.z * 64;

    for (int i = tid; i < 16 * 529; i += 256) Es[i] = emb[i];

    for (int pair = 0; pair < 4; pair++) {
        int bv = bid * 4 + pair;
        int b = bv >> 6, v = bv & 63;
        __syncthreads();
        for (int i = tid; i < 54 * 55; i += 256) img[i] = 0.f;
        __syncthreads();
        float vsc = g_vs[v], vsh = g_vb[v];
        const float* src = g_v + ((size_t)bv << 10);
        for (int i = tid; i < 1024; i += 256) {
            int y = i >> 5, x = i & 31;
            img[(y + PADL) * 55 + x + PADL] = src[i] * vsc + vsh;
        }
        __syncthreads();

        for (int it = 0; it < 4; it++) {
            int task = tid + 256 * it;
            int k = task >> 6;
            int rh = task & 63;
            int row = rh >> 1;
            int xb = (rh & 1) << 4;
            float acc[16] = {};
            const float* ek = Es + k * 529;
            #pragma unroll 1
            for (int i = 0; i < RR; i++) {
                const float* rp = img + (row + i) * 55 + xb;
                float r[38];
                #pragma unroll
                for (int tt = 0; tt < 38; tt++) r[tt] = rp[tt];
                const float* ept = ek + i * RR;
                #pragma unroll
                for (int j = 0; j < RR; j++) {
                    float e = ept[j];
                    #pragma unroll
                    for (int x = 0; x < 16; x++) acc[x] += e * r[j + x];
                }
            }
            int nbase = row * 32 + xb;
            __half* o = g_lph + ((((size_t)(b * 16 + k) << 10) + nbase) << 6) + v;
            #pragma unroll
            for (int x = 0; x < 16; x++) o[(size_t)x << 6] = __float2half(acc[x]);
        }
    }
#endif
}

// ---------------- K6: final contraction ----------------
__global__ __launch_bounds__(256) void k_final(const float* __restrict__ gamma,
                                               float* __restrict__ out)
{
    int b = blockIdx.z;
    int v0 = blockIdx.y * 16;
    int n = blockIdx.x * 256 + threadIdx.x;
    __shared__ float lc_s[256];
    for (int i = threadIdx.x; i < 256; i += 256)
        lc_s[i] = g_lc[b * 1024 + (i >> 4) * 64 + v0 + (i & 15)];
    __syncthreads();
    float qv[64];
    #pragma unroll
    for (int ch = 0; ch < 64; ch++)
        qv[ch] = g_q[(((size_t)b * 64 + ch) << 10) + n] * g_qs[ch] + g_qb[ch];
    float gm = 1.f + gamma[0];
    float y[4][16] = {};
    for (int k = 0; k < 16; k++) {
        const __half2* lp = reinterpret_cast<const __half2*>(
            g_lph + ((((size_t)(b * 16 + k) << 10) + n) << 6) + v0);
        float lam[16];
        #pragma unroll
        for (int j = 0; j < 8; j++) {
            float2 f = __half22float2(lp[j]);
            lam[2 * j] = f.x; lam[2 * j + 1] = f.y;
        }
        #pragma unroll
        for (int jj = 0; jj < 16; jj++) lam[jj] += lc_s[k * 16 + jj];
        #pragma unroll
        for (int h = 0; h < 4; h++) {
            float qh = qv[h * 16 + k];
            #pragma unroll
            for (int jj = 0; jj < 16; jj++) y[h][jj] += qh * lam[jj];
        }
    }
    #pragma unroll
    for (int h = 0; h < 4; h++)
        #pragma unroll
        for (int jj = 0; jj < 16; jj++)
            out[(((size_t)b * 256) + h * 64 + v0 + jj) * NN + n] = y[h][jj] * gm;
}

// ---------------- launch ----------------
extern "C" void kernel_launch(void* const* d_in, const int* in_sizes, int n_in,
                              void* d_out, int out_size)
{
    const float* x      = (const float*)d_in[0];
    const float* Wq     = (const float*)d_in[1];
    const float* bn_q_w = (const float*)d_in[2];
    const float* bn_q_b = (const float*)d_in[3];
    const float* Wk     = (const float*)d_in[4];
    const float* Wv     = (const float*)d_in[5];
    const float* bn_v_w = (const float*)d_in[6];
    const float* bn_v_b = (const float*)d_in[7];
    const float* emb    = (const float*)d_in[8];
    const float* gamma  = (const float*)d_in[9];
    float* out = (float*)d_out;

    cudaFuncSetAttribute(k_gemm, cudaFuncAttributeMaxDynamicSharedMemorySize, GEMM_SMEM);
    cudaFuncSetAttribute(k_proj, cudaFuncAttributeMaxDynamicSharedMemorySize, PROJ_SMEM);

    k_xhalf<<<dim3(16, 4, 32), 256>>>(x);                    // 1
    k_whalf<<<160, 256>>>(Wq, Wk, Wv);                       // 2
    k_buildT<<<32768, 256>>>(emb);                           // 3
    k_proj<<<dim3(8, 32), 128, PROJ_SMEM>>>();               // 4
    k_bnstats<<<128, 256>>>(bn_q_w, bn_q_b, bn_v_w, bn_v_b); // 5
    k_gemm<<<dim3(8, 8, 8), 256, GEMM_SMEM>>>(emb);          // 6
    k_softmax<<<512, 256>>>();                               // 7
    k_lambdac<<<dim3(32, 8), 256>>>();                       // 8
    k_lcred<<<128, 256>>>();                                 // 9
    k_final<<<dim3(4, 4, 32), 256>>>(gamma, out);            // 10
}

// round 7
// speedup vs baseline: 3.9588x; 1.0593x over previous
#include <cuda_runtime.h>
#include <cuda_fp16.h>
#include <cstdint>
#include <math.h>

#define BB 32
#define CC 256
#define NN 1024
#define QCH 64
#define KCH 16
#define VCH 64
#define HEADS 4
#define KD 16
#define RR 23
#define PADL 11
#define EPSB 1e-5f

#if defined(__CUDA_ARCH_FEAT_SM103_ALL) || defined(__CUDA_ARCH_FEAT_SM100_ALL) || \
    defined(__CUDA_ARCH_FEAT_SM101_ALL) || defined(__CUDA_ARCH_SPECIFIC__) || \
    defined(__CUDA_ARCH_FAMILY_SPECIFIC__)
#define USE_TC 1
#else
#define USE_TC 0
#endif

// ---------------- scratch ----------------
__device__ float g_q[BB * QCH * NN];
__device__ float g_k[BB * KCH * NN];
__device__ float g_v[BB * VCH * NN];
__device__ __half g_lph[(size_t)BB * KD * NN * VCH];   // lambda_p fp16 [b][k][n][v]
__device__ float g_lcp[8][BB * KD * VCH];
__device__ float g_qs[QCH], g_qb[QCH];
__device__ float g_vs[VCH], g_vb[VCH];
__device__ __half g_T[(size_t)16 * 1024 * 1024];       // Toeplitz conv matrix fp16
__device__ __half g_vh[(size_t)2048 * 1024];           // BN'd v fp16 [bv][m]
__device__ __half g_xh[(size_t)BB * NN * CC];          // x fp16 [b][n][c]
__device__ __half g_wh[160 * 256];                     // W fp16 [160 pad][256]

// ---------------- PTX helpers ----------------
__device__ __forceinline__ uint32_t smem_u32(const void* p) {
    uint32_t r;
    asm("{ .reg .u64 t; cvta.to.shared.u64 t, %1; cvt.u32.u64 %0, t; }" : "=r"(r) : "l"(p));
    return r;
}
__device__ __forceinline__ void cpasync16(uint32_t s, const void* g) {
    asm volatile("cp.async.cg.shared.global [%0], [%1], 16;" :: "r"(s), "l"(g));
}
#define CP_COMMIT()  asm volatile("cp.async.commit_group;" ::: "memory")
#define CP_WAIT(n)   asm volatile("cp.async.wait_group %0;" :: "n"(n) : "memory")

#if USE_TC
__device__ __forceinline__ uint32_t elect1() {
    uint32_t p;
    asm volatile("{ .reg .pred p; elect.sync _|p, 0xFFFFFFFF; selp.b32 %0,1,0,p; }" : "=r"(p));
    return p;
}
#define MBAR_INIT(a, c) asm volatile("mbarrier.init.shared.b64 [%0], %1;" :: "r"(a), "r"(c) : "memory")
#define MBAR_INVAL(a)   asm volatile("mbarrier.inval.shared.b64 [%0];" :: "r"(a) : "memory")
#define MBAR_WAIT(a, ph) do { \
    uint32_t _m = (a), _p = (ph), _d; \
    asm volatile("{ .reg .pred p; mbarrier.try_wait.parity.acquire.cta.shared::cta.b64 p, [%1], %2; selp.b32 %0,1,0,p; }" \
        : "=r"(_d) : "r"(_m), "r"(_p) : "memory"); \
    if (!_d) { \
        asm volatile("{ .reg .pred P1; WL_%=: mbarrier.try_wait.parity.acquire.cta.shared::cta.b64 P1, [%0], %1, 0x989680; @P1 bra.uni WD_%=; bra.uni WL_%=; WD_%=: }" \
            :: "r"(_m), "r"(_p) : "memory"); \
    } } while (0)

#define TC_ALLOC(sa, n)   asm volatile("tcgen05.alloc.cta_group::1.sync.aligned.shared::cta.b32 [%0], %1;" :: "r"(sa), "r"(n) : "memory")
#define TC_DEALLOC(t, n)  asm volatile("tcgen05.dealloc.cta_group::1.sync.aligned.b32 %0, %1;" :: "r"(t), "r"(n))
#define TC_RELINQ()       asm volatile("tcgen05.relinquish_alloc_permit.cta_group::1.sync.aligned;")
#define TC_COMMIT(mb)     asm volatile("tcgen05.commit.cta_group::1.mbarrier::arrive::one.shared::cluster.b64 [%0];" :: "r"(mb) : "memory")
#define TC_FENCE_AFTER()  asm volatile("tcgen05.fence::after_thread_sync;" ::: "memory")
#define TC_WAIT_LD()      asm volatile("tcgen05.wait::ld.sync.aligned;" ::: "memory")
#define FENCE_ASYNC()     asm volatile("fence.proxy.async.shared::cta;" ::: "memory")

#define TC_LD_X32(r, t) \
    asm volatile("tcgen05.ld.sync.aligned.32x32b.x32.b32 " \
        "{%0,%1,%2,%3,%4,%5,%6,%7,%8,%9,%10,%11,%12,%13,%14,%15," \
        "%16,%17,%18,%19,%20,%21,%22,%23,%24,%25,%26,%27,%28,%29,%30,%31}, [%32];" \
        : "=r"((r)[0]),"=r"((r)[1]),"=r"((r)[2]),"=r"((r)[3]),"=r"((r)[4]),"=r"((r)[5]),"=r"((r)[6]),"=r"((r)[7]), \
          "=r"((r)[8]),"=r"((r)[9]),"=r"((r)[10]),"=r"((r)[11]),"=r"((r)[12]),"=r"((r)[13]),"=r"((r)[14]),"=r"((r)[15]), \
          "=r"((r)[16]),"=r"((r)[17]),"=r"((r)[18]),"=r"((r)[19]),"=r"((r)[20]),"=r"((r)[21]),"=r"((r)[22]),"=r"((r)[23]), \
          "=r"((r)[24]),"=r"((r)[25]),"=r"((r)[26]),"=r"((r)[27]),"=r"((r)[28]),"=r"((r)[29]),"=r"((r)[30]),"=r"((r)[31]) \
        : "r"(t))

__device__ __forceinline__ void mma_f16_ss(uint32_t d, uint64_t ad, uint64_t bd,
                                           uint32_t idesc, uint32_t en) {
    asm volatile(
        "{ .reg .pred p; setp.ne.u32 p, %4, 0;\n\t"
        "tcgen05.mma.cta_group::1.kind::f16 [%0], %1, %2, %3, {%5,%5,%5,%5}, p;\n\t}"
        :: "r"(d), "l"(ad), "l"(bd), "r"(idesc), "r"(en), "r"(0u) : "memory");
}

static constexpr uint64_t DESC_BASE =
    (uint64_t(2) << 61) | (uint64_t(1) << 46) | (uint64_t(64) << 32) | (uint64_t(1) << 16);
__device__ __forceinline__ uint64_t mk_desc(uint32_t a) {
    return DESC_BASE | ((uint64_t)(a >> 4) & 0x3FFF);
}
#endif // USE_TC

// ---------------- K0a: x fp32 -> fp16 transposed [b][n][c] ----------------
__global__ __launch_bounds__(256) void k_xhalf(const float* __restrict__ x)
{
    int b = blockIdx.z, ct = blockIdx.y, nt = blockIdx.x;
    int n0 = nt * 64, c0 = ct * 64;
    __shared__ float s[64][65];
    int tid = threadIdx.x;
    for (int i = tid; i < 64 * 64; i += 256) {
        int c = i >> 6, n = i & 63;
        s[c][n] = x[((size_t)b * 256 + c0 + c) * 1024 + n0 + n];
    }
    __syncthreads();
    for (int i = tid; i < 64 * 32; i += 256) {
        int n = i >> 5, c2 = (i & 31) * 2;
        __half2 h = __floats2half2_rn(s[c2][n], s[c2 + 1][n]);
        *reinterpret_cast<__half2*>(&g_xh[((size_t)b * 1024 + n0 + n) * 256 + c0 + c2]) = h;
    }
}

// ---------------- K0b: pack W into fp16 [160][256] ----------------
__global__ __launch_bounds__(256) void k_whalf(
    const float* __restrict__ Wq, const float* __restrict__ Wk, const float* __restrict__ Wv)
{
    int i = blockIdx.x * 256 + threadIdx.x;
    int row = i >> 8, c = i & 255;
    float val;
    if (row < 64)       val = Wq[row * 256 + c];
    else if (row < 80)  val = Wk[(row - 64) * 256 + c];
    else if (row < 144) val = Wv[(row - 80) * 256 + c];
    else                val = 0.f;
    g_wh[i] = __float2half(val);
}

// ---------------- K1: projections (two M=128 tiles per CTA, shared B) --------
// grid (4 npair, 32 b), 256 threads. A: 8x16KB, B: 4x20KB = 209KB smem.
#define PROJ_SMEM (1024 + 8 * 16384 + 4 * 20480)

__global__ __launch_bounds__(256) void k_proj()
{
#if USE_TC
    extern __shared__ char dsm[];
    __shared__ __align__(16) uint64_t s_mbar;
    __shared__ uint32_t s_tmem;
    int tid = threadIdx.x;
    int wid = tid >> 5, lane = tid & 31;
    int b = blockIdx.y;
    int n0 = blockIdx.x * 256;

    uint32_t raw = smem_u32(dsm);
    uint32_t Ab = (raw + 1023) & ~1023u;
    uint32_t Bb = Ab + 8 * 16384;

    if (wid == 0) { TC_ALLOC(smem_u32(&s_tmem), 512); TC_RELINQ(); }
    if (tid == 0) MBAR_INIT(smem_u32(&s_mbar), 1);
    __syncthreads();
    uint32_t tmem = s_tmem;

    // A: 2 tiles x 4 K-chunks x 128 rows x 8 (16B each)
    for (int i = tid; i < 8192; i += 256) {
        int buf = i >> 10;               // t*4+ch
        int t = buf >> 2, ch = buf & 3;
        int r = (i >> 3) & 127, col = i & 7;
        uint32_t o = r * 128 + col * 16;
        uint32_t sw = o ^ ((o >> 3) & 0x70);
        cpasync16(Ab + buf * 16384 + sw,
                  g_xh + (((size_t)b * 1024 + n0 + t * 128 + r) << 8) + ch * 64 + col * 8);
    }
    // B: 4 K-chunks x 160 rows x 8
    for (int i = tid; i < 5120; i += 256) {
        int ch = i / 1280, rem = i % 1280;
        int r = rem >> 3, col = rem & 7;
        uint32_t o = r * 128 + col * 16;
        uint32_t sw = o ^ ((o >> 3) & 0x70);
        cpasync16(Bb + ch * 20480 + sw, g_wh + r * 256 + ch * 64 + col * 8);
    }
    CP_COMMIT();
    CP_WAIT(0);
    __syncthreads();

    const uint32_t idesc = (1u << 4) | (20u << 17) | (8u << 24);  // F32 acc, f16, N=160, M=128
    if (wid == 0) {
        FENCE_ASYNC();
        if (elect1()) {
            #pragma unroll
            for (int t = 0; t < 2; t++)
                #pragma unroll
                for (int c = 0; c < 4; c++) {
                    uint64_t ad = mk_desc(Ab + (t * 4 + c) * 16384);
                    uint64_t bd = mk_desc(Bb + c * 20480);
                    #pragma unroll
                    for (int ks = 0; ks < 4; ks++)
                        mma_f16_ss(tmem + t * 160, ad + ks * 2, bd + ks * 2, idesc, (c | ks) != 0);
                }
            TC_COMMIT(smem_u32(&s_mbar));
        }
    }
    MBAR_WAIT(smem_u32(&s_mbar), 0);
    TC_FENCE_AFTER();

    int t = wid >> 2;
    int n_g = n0 + t * 128 + (wid & 3) * 32 + lane;
    for (int c0 = 0; c0 < 160; c0 += 32) {
        uint32_t r[32];
        TC_LD_X32(r, tmem + t * 160 + c0);
        TC_WAIT_LD();
        #pragma unroll
        for (int j = 0; j < 32; j++) {
            int ch = c0 + j;
            float val = __uint_as_float(r[j]);
            if (ch < 64)       g_q[(((size_t)b * 64 + ch) << 10) + n_g] = val;
            else if (ch < 80)  g_k[(((size_t)b * 16 + (ch - 64)) << 10) + n_g] = val;
            else if (ch < 144) g_v[(((size_t)b * 64 + (ch - 80)) << 10) + n_g] = val;
        }
    }
    __syncthreads();
    if (tid == 0) MBAR_INVAL(smem_u32(&s_mbar));
    __syncthreads();
    if (wid == 0) TC_DEALLOC(tmem, 512);
#else
    int b = blockIdx.y;
    int n = blockIdx.x * 256 + threadIdx.x;
    const __half* xr = g_xh + (((size_t)b * 1024 + n) << 8);
    for (int ch = 0; ch < 144; ch++) {
        float acc = 0.f;
        for (int c = 0; c < 256; c++)
            acc += __half2float(g_wh[ch * 256 + c]) * __half2float(xr[c]);
        if (ch < 64)       g_q[(((size_t)b * 64 + ch) << 10) + n] = acc;
        else if (ch < 80)  g_k[(((size_t)b * 16 + (ch - 64)) << 10) + n] = acc;
        else               g_v[(((size_t)b * 64 + (ch - 80)) << 10) + n] = acc;
    }
#endif
}

// ---------------- K2: BN stats + fused v->fp16 ----------------
__global__ __launch_bounds__(256) void k_bnstats(
    const float* __restrict__ bnw_q, const float* __restrict__ bnb_q,
    const float* __restrict__ bnw_v, const float* __restrict__ bnb_v)
{
    int ch = blockIdx.x;
    int tid = threadIdx.x;
    const float* src = (ch < 64) ? (g_q + (size_t)ch * NN) : (g_v + (size_t)(ch - 64) * NN);
    float s = 0.f, s2 = 0.f;
    for (int i = tid; i < BB * NN; i += 256) {
        int b = i >> 10, n = i & 1023;
        float v = src[((size_t)b * 64 << 10) + n];
        s += v; s2 += v * v;
    }
    __shared__ float rs[256], rs2[256];
    __shared__ float s_sc, s_sh;
    rs[tid] = s; rs2[tid] = s2;
    __syncthreads();
    for (int st = 128; st > 0; st >>= 1) {
        if (tid < st) { rs[tid] += rs[tid + st]; rs2[tid] += rs2[tid + st]; }
        __syncthreads();
    }
    if (tid == 0) {
        float inv = 1.f / (float)(BB * NN);
        float mean = rs[0] * inv;
        float var = rs2[0] * inv - mean * mean;
        float w, bsh;
        if (ch < 64) { w = bnw_q[ch]; bsh = bnb_q[ch]; }
        else         { w = bnw_v[ch - 64]; bsh = bnb_v[ch - 64]; }
        float sc = w * rsqrtf(var + EPSB);
        float sh = bsh - mean * sc;
        if (ch < 64) { g_qs[ch] = sc; g_qb[ch] = sh; }
        else         { g_vs[ch - 64] = sc; g_vb[ch - 64] = sh; }
        s_sc = sc; s_sh = sh;
    }
    __syncthreads();
    if (ch >= 64) {
        int v = ch - 64;
        float sc = s_sc, sh = s_sh;
        for (int i = tid; i < BB * NN; i += 256) {
            int b = i >> 10, n = i & 1023;
            float val = src[((size_t)b * 64 << 10) + n];
            g_vh[(((size_t)(b * 64 + v)) << 10) + n] = __float2half(val * sc + sh);
        }
    }
}

// ---------------- K2b: softmax ----------------
__global__ __launch_bounds__(256) void k_softmax()
{
    int row = blockIdx.x;
    float* p = g_k + ((size_t)row << 10);
    int tid = threadIdx.x;
    float v0 = p[tid], v1 = p[tid + 256], v2 = p[tid + 512], v3 = p[tid + 768];
    __shared__ float red[256];
    float mx = fmaxf(fmaxf(v0, v1), fmaxf(v2, v3));
    red[tid] = mx; __syncthreads();
    for (int st = 128; st > 0; st >>= 1) {
        if (tid < st) red[tid] = fmaxf(red[tid], red[tid + st]);
        __syncthreads();
    }
    mx = red[0]; __syncthreads();
    v0 = expf(v0 - mx); v1 = expf(v1 - mx); v2 = expf(v2 - mx); v3 = expf(v3 - mx);
    red[tid] = v0 + v1 + v2 + v3; __syncthreads();
    for (int st = 128; st > 0; st >>= 1) {
        if (tid < st) red[tid] += red[tid + st];
        __syncthreads();
    }
    float inv = 1.f / red[0];
    p[tid] = v0 * inv; p[tid + 256] = v1 * inv; p[tid + 512] = v2 * inv; p[tid + 768] = v3 * inv;
}

// ---------------- K3: lambda_c partials ----------------
__global__ __launch_bounds__(256) void k_lambdac()
{
    int b = blockIdx.x;
    int part = blockIdx.y;
    int nc = part * 128;
    int tid = threadIdx.x;
    int s = tid >> 6, v = tid & 63;
    __shared__ float sbuf[16 * 128 + 128 * 65];
    float* sm_s = sbuf;
    float* vs_s = sbuf + 16 * 128;

    for (int i = tid; i < 16 * 128; i += 256) {
        int k = i >> 7, nn = i & 127;
        sm_s[k * 128 + nn] = g_k[(((size_t)b * 16 + k) << 10) + nc + nn];
    }
    for (int i = tid; i < 64 * 128; i += 256) {
        int vv = i >> 7, nn = i & 127;
        vs_s[nn * 65 + vv] = __half2float(g_vh[(((size_t)b * 64 + vv) << 10) + nc + nn]);
    }
    __syncthreads();
    float acc[16] = {};
    for (int nn = s * 32; nn < s * 32 + 32; nn++) {
        float vv = vs_s[nn * 65 + v];
        #pragma unroll
        for (int k = 0; k < 16; k++) acc[k] += sm_s[k * 128 + nn] * vv;
    }
    __syncthreads();
    #pragma unroll
    for (int k = 0; k < 16; k++) sbuf[s * 1024 + k * 64 + v] = acc[k];
    __syncthreads();
    for (int e = tid; e < 1024; e += 256)
        g_lcp[part][b * 1024 + e] = sbuf[e] + sbuf[1024 + e] + sbuf[2048 + e] + sbuf[3072 + e];
}

// ---------------- K4: build fp16 Toeplitz matrix T (band-skip) ----------------
__global__ __launch_bounds__(256) void k_buildT(const float* __restrict__ emb)
{
    size_t i = (size_t)blockIdx.x * 256 + threadIdx.x;
    int k = (int)(i >> 19);
    int rem = (int)(i & 0x7FFFF);
    int n = rem >> 9;
    int m0 = (rem & 511) * 2;
    // skip chunks never read by k_gemm's band loop (same formula)
    {
        int y0t = (n >> 7) * 4;
        int clo = (y0t > 11) ? ((y0t - 11) >> 1) : 0;
        int chi = min(15, (y0t + 14) >> 1);
        int ch = m0 >> 6;
        if (ch < clo || ch > chi) return;
    }
    int yn = n >> 5, xn = n & 31;
    float f[2];
    #pragma unroll
    for (int e = 0; e < 2; e++) {
        int mm = m0 + e;
        int dy = (mm >> 5) - yn + 11;
        int dx = (mm & 31) - xn + 11;
        f[e] = ((unsigned)dy < 23u && (unsigned)dx < 23u) ? emb[k * 529 + dy * 23 + dx] : 0.f;
    }
    __half2 h = __floats2half2_rn(f[0], f[1]);
    *reinterpret_cast<__half2*>(g_T + (((size_t)k << 20) + ((size_t)n << 10) + m0)) = h;
}

// ---------------- K5: lambda_p GEMM (decoupled pipeline + band skip) ----------
#define GEMM_SMEM (1024 + 3 * 65536)

__global__ __launch_bounds__(256) void k_gemm(const float* __restrict__ emb)
{
#if USE_TC
    extern __shared__ char dsm[];
    __shared__ __align__(16) uint64_t s_mbar[3];
    __shared__ uint32_t s_tmem;

    int tid = threadIdx.x;
    int wid = tid >> 5, lane = tid & 31;
    int kg = blockIdx.z;
    int n0 = blockIdx.x * 128;
    int bv0 = blockIdx.y * 256;

    int y0 = blockIdx.x * 4;
    int c_lo = (y0 > 11) ? ((y0 - 11) >> 1) : 0;
    int c_hi = min(15, (y0 + 14) >> 1);
    int nch = c_hi - c_lo + 1;     // 8..14

    uint32_t raw = smem_u32(dsm);
    uint32_t abase = (raw + 1023) & ~1023u;

    if (wid == 0) { TC_ALLOC(smem_u32(&s_tmem), 512); TC_RELINQ(); }
    if (tid == 0) {
        MBAR_INIT(smem_u32(&s_mbar[0]), 1);
        MBAR_INIT(smem_u32(&s_mbar[1]), 1);
        MBAR_INIT(smem_u32(&s_mbar[2]), 1);
    }
    __syncthreads();
    uint32_t tmem = s_tmem;

    const __half* Tk0 = g_T + ((size_t)(2 * kg) << 20);
    const __half* Tk1 = g_T + ((size_t)(2 * kg + 1) << 20);

    #define ISSUE_LOADS(chunk, stage) do {                                            \
        int _m0 = (chunk) * 64;                                                       \
        uint32_t _Sb = abase + (stage) * 65536;                                       \
        for (int _i = tid; _i < 1024; _i += 256) {                                    \
            int _r = _i >> 3, _c = _i & 7;                                            \
            uint32_t _o = _r * 128 + _c * 16;                                         \
            uint32_t _s = _o ^ ((_o >> 3) & 0x70);                                    \
            cpasync16(_Sb + _s, Tk0 + (((size_t)(n0 + _r) << 10) + _m0 + _c * 8));    \
        }                                                                             \
        for (int _i = tid; _i < 1024; _i += 256) {                                    \
            int _r = _i >> 3, _c = _i & 7;                                            \
            uint32_t _o = _r * 128 + _c * 16;                                         \
            uint32_t _s = _o ^ ((_o >> 3) & 0x70);                                    \
            cpasync16(_Sb + 16384 + _s, Tk1 + (((size_t)(n0 + _r) << 10) + _m0 + _c * 8)); \
        }                                                                             \
        for (int _i = tid; _i < 2048; _i += 256) {                                    \
            int _r = _i >> 3, _c = _i & 7;                                            \
            uint32_t _o = _r * 128 + _c * 16;                                         \
            uint32_t _s = _o ^ ((_o >> 3) & 0x70);                                    \
            cpasync16(_Sb + 32768 + _s, g_vh + (((size_t)(bv0 + _r) << 10) + _m0 + _c * 8)); \
        }                                                                             \
    } while (0)

    ISSUE_LOADS(c_lo + 0, 0); CP_COMMIT();
    ISSUE_LOADS(c_lo + 1, 1); CP_COMMIT();
    ISSUE_LOADS(c_lo + 2, 2); CP_COMMIT();

    const uint32_t idesc = (1u << 4) | (32u << 17) | (8u << 24);  // F32 acc, f16, N=256, M=128
    uint32_t php0 = 0, php1 = 0, php2 = 0;

    for (int ci = 0; ci < nch; ci++) {
        int s = ci - (ci / 3) * 3;
        if (ci == 0)            CP_WAIT(2);
        else if (ci == nch - 1) CP_WAIT(0);
        else                    CP_WAIT(1);
        __syncthreads();
        if (wid == 0) {
            FENCE_ASYNC();
            if (elect1()) {
                uint32_t sb = abase + s * 65536;
                uint64_t a0 = mk_desc(sb);
                uint64_t a1 = mk_desc(sb + 16384);
                uint64_t bd = mk_desc(sb + 32768);
                #pragma unroll
                for (int ks = 0; ks < 4; ks++) {
                    uint32_t en = (ci | ks) != 0;
                    mma_f16_ss(tmem,       a0 + ks * 2, bd + ks * 2, idesc, en);
                    mma_f16_ss(tmem + 256, a1 + ks * 2, bd + ks * 2, idesc, en);
                }
                TC_COMMIT(smem_u32(&s_mbar[s]));
            }
        }
        // deferred refill: stage of chunk ci-1, loads chunk ci+2.
        // MMA(ci) already queued above -> the wait below overlaps with it.
        if (ci >= 1 && ci + 2 < nch) {
            int sp = (ci - 1) - ((ci - 1) / 3) * 3;
            uint32_t ph = (sp == 0) ? php0 : (sp == 1) ? php1 : php2;
            MBAR_WAIT(smem_u32(&s_mbar[sp]), ph);
            if (sp == 0) php0 ^= 1; else if (sp == 1) php1 ^= 1; else php2 ^= 1;
            ISSUE_LOADS(c_lo + ci + 2, sp);
            CP_COMMIT();
        }
    }
    // drain the three un-waited commits
    MBAR_WAIT(smem_u32(&s_mbar[0]), php0);
    MBAR_WAIT(smem_u32(&s_mbar[1]), php1);
    MBAR_WAIT(smem_u32(&s_mbar[2]), php2);
    TC_FENCE_AFTER();

    // epilogue: two D tiles -> g_lph fp16 [b][k][n][v]
    int t = wid >> 2;
    int kk = 2 * kg + t;
    int n_g = n0 + (wid & 3) * 32 + lane;
    for (int c0 = 0; c0 < 256; c0 += 32) {
        uint32_t r[32];
        TC_LD_X32(r, tmem + t * 256 + c0);
        TC_WAIT_LD();
        int bvb = bv0 + c0;
        int b = bvb >> 6, vb = bvb & 63;
        uint32_t h2[16];
        #pragma unroll
        for (int j = 0; j < 16; j++) {
            __half2 h = __floats2half2_rn(__uint_as_float(r[2 * j]), __uint_as_float(r[2 * j + 1]));
            h2[j] = *reinterpret_cast<uint32_t*>(&h);
        }
        __half* dst = g_lph + ((((size_t)(b * 16 + kk) << 10) + n_g) << 6) + vb;
        uint4* d4 = reinterpret_cast<uint4*>(dst);
        #pragma unroll
        for (int q4 = 0; q4 < 4; q4++)
            d4[q4] = make_uint4(h2[4 * q4], h2[4 * q4 + 1], h2[4 * q4 + 2], h2[4 * q4 + 3]);
    }
    __syncthreads();
    if (tid == 0) {
        MBAR_INVAL(smem_u32(&s_mbar[0]));
        MBAR_INVAL(smem_u32(&s_mbar[1]));
        MBAR_INVAL(smem_u32(&s_mbar[2]));
    }
    __syncthreads();
    if (wid == 0) TC_DEALLOC(tmem, 512);
    #undef ISSUE_LOADS

#else  // ---- fallback: scalar direct conv ----
    extern __shared__ char dsm[];
    float* img = (float*)dsm;
    float* Es  = img + 54 * 55;
    int tid = threadIdx.x;
    int bid = blockIdx.x + blockIdx.y * 8 + blockIdx.z * 64;

    for (int i = tid; i < 16 * 529; i += 256) Es[i] = emb[i];

    for (int pair = 0; pair < 4; pair++) {
        int bv = bid * 4 + pair;
        int b = bv >> 6, v = bv & 63;
        __syncthreads();
        for (int i = tid; i < 54 * 55; i += 256) img[i] = 0.f;
        __syncthreads();
        float vsc = g_vs[v], vsh = g_vb[v];
        const float* src = g_v + ((size_t)bv << 10);
        for (int i = tid; i < 1024; i += 256) {
            int y = i >> 5, x = i & 31;
            img[(y + PADL) * 55 + x + PADL] = src[i] * vsc + vsh;
        }
        __syncthreads();

        for (int it = 0; it < 4; it++) {
            int task = tid + 256 * it;
            int k = task >> 6;
            int rh = task & 63;
            int row = rh >> 1;
            int xb = (rh & 1) << 4;
            float acc[16] = {};
            const float* ek = Es + k * 529;
            #pragma unroll 1
            for (int i = 0; i < RR; i++) {
                const float* rp = img + (row + i) * 55 + xb;
                float r[38];
                #pragma unroll
                for (int tt = 0; tt < 38; tt++) r[tt] = rp[tt];
                const float* ept = ek + i * RR;
                #pragma unroll
                for (int j = 0; j < RR; j++) {
                    float e = ept[j];
                    #pragma unroll
                    for (int x = 0; x < 16; x++) acc[x] += e * r[j + x];
                }
            }
            int nbase = row * 32 + xb;
            __half* o = g_lph + ((((size_t)(b * 16 + k) << 10) + nbase) << 6) + v;
            #pragma unroll
            for (int x = 0; x < 16; x++) o[(size_t)x << 6] = __float2half(acc[x]);
        }
    }
#endif
}

// ---------------- K6: final contraction (lambda_c reduce fused in) -----------
__global__ __launch_bounds__(256) void k_final(const float* __restrict__ gamma,
                                               float* __restrict__ out)
{
    int b = blockIdx.z;
    int v0 = blockIdx.y * 16;
    int n = blockIdx.x * 256 + threadIdx.x;
    __shared__ float lc_s[256];
    for (int i = threadIdx.x; i < 256; i += 256) {
        int idx = b * 1024 + (i >> 4) * 64 + v0 + (i & 15);
        float sum = 0.f;
        #pragma unroll
        for (int p = 0; p < 8; p++) sum += g_lcp[p][idx];
        lc_s[i] = sum;
    }
    __syncthreads();
    float qv[64];
    #pragma unroll
    for (int ch = 0; ch < 64; ch++)
        qv[ch] = g_q[(((size_t)b * 64 + ch) << 10) + n] * g_qs[ch] + g_qb[ch];
    float gm = 1.f + gamma[0];
    float y[4][16] = {};
    for (int k = 0; k < 16; k++) {
        const __half2* lp = reinterpret_cast<const __half2*>(
            g_lph + ((((size_t)(b * 16 + k) << 10) + n) << 6) + v0);
        float lam[16];
        #pragma unroll
        for (int j = 0; j < 8; j++) {
            float2 f = __half22float2(lp[j]);
            lam[2 * j] = f.x; lam[2 * j + 1] = f.y;
        }
        #pragma unroll
        for (int jj = 0; jj < 16; jj++) lam[jj] += lc_s[k * 16 + jj];
        #pragma unroll
        for (int h = 0; h < 4; h++) {
            float qh = qv[h * 16 + k];
            #pragma unroll
            for (int jj = 0; jj < 16; jj++) y[h][jj] += qh * lam[jj];
        }
    }
    #pragma unroll
    for (int h = 0; h < 4; h++)
        #pragma unroll
        for (int jj = 0; jj < 16; jj++)
            out[(((size_t)b * 256) + h * 64 + v0 + jj) * NN + n] = y[h][jj] * gm;
}

// ---------------- launch ----------------
extern "C" void kernel_launch(void* const* d_in, const int* in_sizes, int n_in,
                              void* d_out, int out_size)
{
    const float* x      = (const float*)d_in[0];
    const float* Wq     = (const float*)d_in[1];
    const float* bn_q_w = (const float*)d_in[2];
    const float* bn_q_b = (const float*)d_in[3];
    const float* Wk     = (const float*)d_in[4];
    const float* Wv     = (const float*)d_in[5];
    const float* bn_v_w = (const float*)d_in[6];
    const float* bn_v_b = (const float*)d_in[7];
    const float* emb    = (const float*)d_in[8];
    const float* gamma  = (const float*)d_in[9];
    float* out = (float*)d_out;

    cudaFuncSetAttribute(k_gemm, cudaFuncAttributeMaxDynamicSharedMemorySize, GEMM_SMEM);
    cudaFuncSetAttribute(k_proj, cudaFuncAttributeMaxDynamicSharedMemorySize, PROJ_SMEM);

    k_xhalf<<<dim3(16, 4, 32), 256>>>(x);
    k_whalf<<<160, 256>>>(Wq, Wk, Wv);
    k_buildT<<<32768, 256>>>(emb);
    k_proj<<<dim3(4, 32), 256, PROJ_SMEM>>>();
    k_bnstats<<<128, 256>>>(bn_q_w, bn_q_b, bn_v_w, bn_v_b);
    k_gemm<<<dim3(8, 8, 8), 256, GEMM_SMEM>>>(emb);
    k_softmax<<<512, 256>>>();
    k_lambdac<<<dim3(32, 8), 256>>>();
    k_final<<<dim3(4, 4, 32), 256>>>(gamma, out);
}

// round 9
// speedup vs baseline: 4.0247x; 1.0167x over previous
#include <cuda_runtime.h>
#include <cuda_fp16.h>
#include <cstdint>
#include <math.h>

#define BB 32
#define CC 256
#define NN 1024
#define QCH 64
#define KCH 16
#define VCH 64
#define HEADS 4
#define KD 16
#define RR 23
#define PADL 11
#define EPSB 1e-5f

#if defined(__CUDA_ARCH_FEAT_SM103_ALL) || defined(__CUDA_ARCH_FEAT_SM100_ALL) || \
    defined(__CUDA_ARCH_FEAT_SM101_ALL) || defined(__CUDA_ARCH_SPECIFIC__) || \
    defined(__CUDA_ARCH_FAMILY_SPECIFIC__)
#define USE_TC 1
#else
#define USE_TC 0
#endif

// ---------------- scratch ----------------
__device__ float g_q[BB * QCH * NN];
__device__ float g_k[BB * KCH * NN];                   // raw (pre-softmax) k
__device__ float g_v[BB * VCH * NN];
__device__ __half g_lph[(size_t)BB * KD * NN * VCH];   // lambda_p fp16 [b][k][n][v]
__device__ float g_lcp[8][BB * KD * VCH];
__device__ float g_qs[QCH], g_qb[QCH];
__device__ float g_vs[VCH], g_vb[VCH];
__device__ float g_smx[BB * KD], g_smi[BB * KD];       // softmax row max / 1/sum
__device__ __half g_T[(size_t)16 * 1024 * 1024];       // Toeplitz conv matrix fp16
__device__ __half g_vh[(size_t)2048 * 1024];           // BN'd v fp16 [bv][m]
__device__ __half g_xh[(size_t)BB * NN * CC];          // x fp16 [b][n][c]
__device__ __half g_wh[160 * 256];                     // W fp16 [160 pad][256]

// ---------------- PTX helpers ----------------
__device__ __forceinline__ uint32_t smem_u32(const void* p) {
    uint32_t r;
    asm("{ .reg .u64 t; cvta.to.shared.u64 t, %1; cvt.u32.u64 %0, t; }" : "=r"(r) : "l"(p));
    return r;
}
__device__ __forceinline__ void cpasync16(uint32_t s, const void* g) {
    asm volatile("cp.async.cg.shared.global [%0], [%1], 16;" :: "r"(s), "l"(g));
}
#define CP_COMMIT()  asm volatile("cp.async.commit_group;" ::: "memory")
#define CP_WAIT(n)   asm volatile("cp.async.wait_group %0;" :: "n"(n) : "memory")

#if USE_TC
__device__ __forceinline__ uint32_t elect1() {
    uint32_t p;
    asm volatile("{ .reg .pred p; elect.sync _|p, 0xFFFFFFFF; selp.b32 %0,1,0,p; }" : "=r"(p));
    return p;
}
#define MBAR_INIT(a, c) asm volatile("mbarrier.init.shared.b64 [%0], %1;" :: "r"(a), "r"(c) : "memory")
#define MBAR_INVAL(a)   asm volatile("mbarrier.inval.shared.b64 [%0];" :: "r"(a) : "memory")
#define MBAR_WAIT(a, ph) do { \
    uint32_t _m = (a), _p = (ph), _d; \
    asm volatile("{ .reg .pred p; mbarrier.try_wait.parity.acquire.cta.shared::cta.b64 p, [%1], %2; selp.b32 %0,1,0,p; }" \
        : "=r"(_d) : "r"(_m), "r"(_p) : "memory"); \
    if (!_d) { \
        asm volatile("{ .reg .pred P1; WL_%=: mbarrier.try_wait.parity.acquire.cta.shared::cta.b64 P1, [%0], %1, 0x989680; @P1 bra.uni WD_%=; bra.uni WL_%=; WD_%=: }" \
            :: "r"(_m), "r"(_p) : "memory"); \
    } } while (0)

#define TC_ALLOC(sa, n)   asm volatile("tcgen05.alloc.cta_group::1.sync.aligned.shared::cta.b32 [%0], %1;" :: "r"(sa), "r"(n) : "memory")
#define TC_DEALLOC(t, n)  asm volatile("tcgen05.dealloc.cta_group::1.sync.aligned.b32 %0, %1;" :: "r"(t), "r"(n))
#define TC_RELINQ()       asm volatile("tcgen05.relinquish_alloc_permit.cta_group::1.sync.aligned;")
#define TC_COMMIT(mb)     asm volatile("tcgen05.commit.cta_group::1.mbarrier::arrive::one.shared::cluster.b64 [%0];" :: "r"(mb) : "memory")
#define TC_FENCE_AFTER()  asm volatile("tcgen05.fence::after_thread_sync;" ::: "memory")
#define TC_WAIT_LD()      asm volatile("tcgen05.wait::ld.sync.aligned;" ::: "memory")
#define FENCE_ASYNC()     asm volatile("fence.proxy.async.shared::cta;" ::: "memory")

#define TC_LD_X32(r, t) \
    asm volatile("tcgen05.ld.sync.aligned.32x32b.x32.b32 " \
        "{%0,%1,%2,%3,%4,%5,%6,%7,%8,%9,%10,%11,%12,%13,%14,%15," \
        "%16,%17,%18,%19,%20,%21,%22,%23,%24,%25,%26,%27,%28,%29,%30,%31}, [%32];" \
        : "=r"((r)[0]),"=r"((r)[1]),"=r"((r)[2]),"=r"((r)[3]),"=r"((r)[4]),"=r"((r)[5]),"=r"((r)[6]),"=r"((r)[7]), \
          "=r"((r)[8]),"=r"((r)[9]),"=r"((r)[10]),"=r"((r)[11]),"=r"((r)[12]),"=r"((r)[13]),"=r"((r)[14]),"=r"((r)[15]), \
          "=r"((r)[16]),"=r"((r)[17]),"=r"((r)[18]),"=r"((r)[19]),"=r"((r)[20]),"=r"((r)[21]),"=r"((r)[22]),"=r"((r)[23]), \
          "=r"((r)[24]),"=r"((r)[25]),"=r"((r)[26]),"=r"((r)[27]),"=r"((r)[28]),"=r"((r)[29]),"=r"((r)[30]),"=r"((r)[31]) \
        : "r"(t))

__device__ __forceinline__ void mma_f16_ss(uint32_t d, uint64_t ad, uint64_t bd,
                                           uint32_t idesc, uint32_t en) {
    asm volatile(
        "{ .reg .pred p; setp.ne.u32 p, %4, 0;\n\t"
        "tcgen05.mma.cta_group::1.kind::f16 [%0], %1, %2, %3, {%5,%5,%5,%5}, p;\n\t}"
        :: "r"(d), "l"(ad), "l"(bd), "r"(idesc), "r"(en), "r"(0u) : "memory");
}

static constexpr uint64_t DESC_BASE =
    (uint64_t(2) << 61) | (uint64_t(1) << 46) | (uint64_t(64) << 32) | (uint64_t(1) << 16);
__device__ __forceinline__ uint64_t mk_desc(uint32_t a) {
    return DESC_BASE | ((uint64_t)(a >> 4) & 0x3FFF);
}
#endif // USE_TC

// ---------------- K0: merged prep (xhalf | whalf | buildT) ----------------
// blocks [0,2048): xhalf; [2048,2208): whalf; [2208,34976): buildT
__global__ __launch_bounds__(256) void k_prep(
    const float* __restrict__ x, const float* __restrict__ Wq,
    const float* __restrict__ Wk, const float* __restrict__ Wv,
    const float* __restrict__ emb)
{
    int blk = blockIdx.x;
    int tid = threadIdx.x;
    if (blk < 2048) {
        // ---- xhalf: fp32 [b][c][n] -> fp16 [b][n][c] ----
        int nt = blk & 15, ct = (blk >> 4) & 3, b = blk >> 6;
        int n0 = nt * 64, c0 = ct * 64;
        __shared__ float s[64][65];
        for (int i = tid; i < 64 * 64; i += 256) {
            int c = i >> 6, n = i & 63;
            s[c][n] = x[((size_t)b * 256 + c0 + c) * 1024 + n0 + n];
        }
        __syncthreads();
        for (int i = tid; i < 64 * 32; i += 256) {
            int n = i >> 5, c2 = (i & 31) * 2;
            __half2 h = __floats2half2_rn(s[c2][n], s[c2 + 1][n]);
            *reinterpret_cast<__half2*>(&g_xh[((size_t)b * 1024 + n0 + n) * 256 + c0 + c2]) = h;
        }
    } else if (blk < 2208) {
        // ---- whalf ----
        int i = (blk - 2048) * 256 + tid;
        int row = i >> 8, c = i & 255;
        float val;
        if (row < 64)       val = Wq[row * 256 + c];
        else if (row < 80)  val = Wk[(row - 64) * 256 + c];
        else if (row < 144) val = Wv[(row - 80) * 256 + c];
        else                val = 0.f;
        g_wh[i] = __float2half(val);
    } else {
        // ---- buildT (band-skip) ----
        size_t i = (size_t)(blk - 2208) * 256 + tid;
        int k = (int)(i >> 19);
        int rem = (int)(i & 0x7FFFF);
        int n = rem >> 9;
        int m0 = (rem & 511) * 2;
        {
            int y0t = (n >> 7) * 4;
            int clo = (y0t > 11) ? ((y0t - 11) >> 1) : 0;
            int chi = min(15, (y0t + 14) >> 1);
            int ch = m0 >> 6;
            if (ch < clo || ch > chi) return;
        }
        int yn = n >> 5, xn = n & 31;
        float f[2];
        #pragma unroll
        for (int e = 0; e < 2; e++) {
            int mm = m0 + e;
            int dy = (mm >> 5) - yn + 11;
            int dx = (mm & 31) - xn + 11;
            f[e] = ((unsigned)dy < 23u && (unsigned)dx < 23u) ? emb[k * 529 + dy * 23 + dx] : 0.f;
        }
        __half2 h = __floats2half2_rn(f[0], f[1]);
        *reinterpret_cast<__half2*>(g_T + (((size_t)k << 20) + ((size_t)n << 10) + m0)) = h;
    }
}

// ---------------- K1: projections (pipelined chunk loads) --------
#define PROJ_SMEM (1024 + 8 * 16384 + 4 * 20480)

__global__ __launch_bounds__(256) void k_proj()
{
#if USE_TC
    extern __shared__ char dsm[];
    __shared__ __align__(16) uint64_t s_mbar;
    __shared__ uint32_t s_tmem;
    int tid = threadIdx.x;
    int wid = tid >> 5, lane = tid & 31;
    int b = blockIdx.y;
    int n0 = blockIdx.x * 256;

    uint32_t raw = smem_u32(dsm);
    uint32_t Ab = (raw + 1023) & ~1023u;
    uint32_t Bb = Ab + 8 * 16384;

    if (wid == 0) { TC_ALLOC(smem_u32(&s_tmem), 512); TC_RELINQ(); }
    if (tid == 0) MBAR_INIT(smem_u32(&s_mbar), 1);
    __syncthreads();
    uint32_t tmem = s_tmem;

    // per-chunk commit groups: A tile0 chunk + A tile1 chunk + B chunk
    for (int c = 0; c < 4; c++) {
        #pragma unroll
        for (int t = 0; t < 2; t++)
            for (int i = tid; i < 1024; i += 256) {
                int r = i >> 3, col = i & 7;
                uint32_t o = r * 128 + col * 16;
                uint32_t sw = o ^ ((o >> 3) & 0x70);
                cpasync16(Ab + (t * 4 + c) * 16384 + sw,
                          g_xh + (((size_t)b * 1024 + n0 + t * 128 + r) << 8) + c * 64 + col * 8);
            }
        for (int i = tid; i < 1280; i += 256) {
            int r = i >> 3, col = i & 7;
            uint32_t o = r * 128 + col * 16;
            uint32_t sw = o ^ ((o >> 3) & 0x70);
            cpasync16(Bb + c * 20480 + sw, g_wh + r * 256 + c * 64 + col * 8);
        }
        CP_COMMIT();
    }

    const uint32_t idesc = (1u << 4) | (20u << 17) | (8u << 24);  // F32 acc, f16, N=160, M=128
    for (int c = 0; c < 4; c++) {
        if (c == 0)      CP_WAIT(3);
        else if (c == 1) CP_WAIT(2);
        else if (c == 2) CP_WAIT(1);
        else             CP_WAIT(0);
        __syncthreads();
        if (wid == 0) {
            FENCE_ASYNC();
            if (elect1()) {
                #pragma unroll
                for (int t = 0; t < 2; t++) {
                    uint64_t ad = mk_desc(Ab + (t * 4 + c) * 16384);
                    uint64_t bd = mk_desc(Bb + c * 20480);
                    #pragma unroll
                    for (int ks = 0; ks < 4; ks++)
                        mma_f16_ss(tmem + t * 160, ad + ks * 2, bd + ks * 2, idesc, (c | ks) != 0);
                }
                if (c == 3) TC_COMMIT(smem_u32(&s_mbar));
            }
        }
    }
    MBAR_WAIT(smem_u32(&s_mbar), 0);
    TC_FENCE_AFTER();

    int t = wid >> 2;
    int n_g = n0 + t * 128 + (wid & 3) * 32 + lane;
    for (int c0 = 0; c0 < 160; c0 += 32) {
        uint32_t r[32];
        TC_LD_X32(r, tmem + t * 160 + c0);
        TC_WAIT_LD();
        #pragma unroll
        for (int j = 0; j < 32; j++) {
            int ch = c0 + j;
            float val = __uint_as_float(r[j]);
            if (ch < 64)       g_q[(((size_t)b * 64 + ch) << 10) + n_g] = val;
            else if (ch < 80)  g_k[(((size_t)b * 16 + (ch - 64)) << 10) + n_g] = val;
            else if (ch < 144) g_v[(((size_t)b * 64 + (ch - 80)) << 10) + n_g] = val;
        }
    }
    __syncthreads();
    if (tid == 0) MBAR_INVAL(smem_u32(&s_mbar));
    __syncthreads();
    if (wid == 0) TC_DEALLOC(tmem, 512);
#else
    int b = blockIdx.y;
    int n = blockIdx.x * 256 + threadIdx.x;
    const __half* xr = g_xh + (((size_t)b * 1024 + n) << 8);
    for (int ch = 0; ch < 144; ch++) {
        float acc = 0.f;
        for (int c = 0; c < 256; c++)
            acc += __half2float(g_wh[ch * 256 + c]) * __half2float(xr[c]);
        if (ch < 64)       g_q[(((size_t)b * 64 + ch) << 10) + n] = acc;
        else if (ch < 80)  g_k[(((size_t)b * 16 + (ch - 64)) << 10) + n] = acc;
        else               g_v[(((size_t)b * 64 + (ch - 80)) << 10) + n] = acc;
    }
#endif
}

// ---------------- K2: BN stats + fused v->fp16 ----------------
__global__ __launch_bounds__(256) void k_bnstats(
    const float* __restrict__ bnw_q, const float* __restrict__ bnb_q,
    const float* __restrict__ bnw_v, const float* __restrict__ bnb_v)
{
    int ch = blockIdx.x;
    int tid = threadIdx.x;
    const float* src = (ch < 64) ? (g_q + (size_t)ch * NN) : (g_v + (size_t)(ch - 64) * NN);
    float s = 0.f, s2 = 0.f;
    for (int i = tid; i < BB * NN; i += 256) {
        int b = i >> 10, n = i & 1023;
        float v = src[((size_t)b * 64 << 10) + n];
        s += v; s2 += v * v;
    }
    __shared__ float rs[256], rs2[256];
    __shared__ float s_sc, s_sh;
    rs[tid] = s; rs2[tid] = s2;
    __syncthreads();
    for (int st = 128; st > 0; st >>= 1) {
        if (tid < st) { rs[tid] += rs[tid + st]; rs2[tid] += rs2[tid + st]; }
        __syncthreads();
    }
    if (tid == 0) {
        float inv = 1.f / (float)(BB * NN);
        float mean = rs[0] * inv;
        float var = rs2[0] * inv - mean * mean;
        float w, bsh;
        if (ch < 64) { w = bnw_q[ch]; bsh = bnb_q[ch]; }
        else         { w = bnw_v[ch - 64]; bsh = bnb_v[ch - 64]; }
        float sc = w * rsqrtf(var + EPSB);
        float sh = bsh - mean * sc;
        if (ch < 64) { g_qs[ch] = sc; g_qb[ch] = sh; }
        else         { g_vs[ch - 64] = sc; g_vb[ch - 64] = sh; }
        s_sc = sc; s_sh = sh;
    }
    __syncthreads();
    if (ch >= 64) {
        int v = ch - 64;
        float sc = s_sc, sh = s_sh;
        for (int i = tid; i < BB * NN; i += 256) {
            int b = i >> 10, n = i & 1023;
            float val = src[((size_t)b * 64 << 10) + n];
            g_vh[(((size_t)(b * 64 + v)) << 10) + n] = __float2half(val * sc + sh);
        }
    }
}

// ---------------- K2b: softmax row stats (max, 1/sum) ----------------
__global__ __launch_bounds__(128) void k_smstats()
{
    int row = blockIdx.x * 4 + (threadIdx.x >> 5);   // 512 rows
    int lane = threadIdx.x & 31;
    const float* p = g_k + ((size_t)row << 10);
    float mx = -1e30f;
    for (int i = lane; i < 1024; i += 32) mx = fmaxf(mx, p[i]);
    #pragma unroll
    for (int o = 16; o; o >>= 1) mx = fmaxf(mx, __shfl_xor_sync(~0u, mx, o));
    float s = 0.f;
    for (int i = lane; i < 1024; i += 32) s += expf(p[i] - mx);
    #pragma unroll
    for (int o = 16; o; o >>= 1) s += __shfl_xor_sync(~0u, s, o);
    if (lane == 0) { g_smx[row] = mx; g_smi[row] = 1.f / s; }
}

// ---------------- K3: lambda_c partials (softmax applied on the fly) ----------
__global__ __launch_bounds__(256) void k_lambdac()
{
    int b = blockIdx.x;
    int part = blockIdx.y;
    int nc = part * 128;
    int tid = threadIdx.x;
    int s = tid >> 6, v = tid & 63;
    __shared__ float sbuf[16 * 128 + 128 * 65];
    __shared__ float s_mx[16], s_mi[16];
    float* sm_s = sbuf;
    float* vs_s = sbuf + 16 * 128;

    if (tid < 16) { s_mx[tid] = g_smx[b * 16 + tid]; s_mi[tid] = g_smi[b * 16 + tid]; }
    __syncthreads();

    for (int i = tid; i < 16 * 128; i += 256) {
        int k = i >> 7, nn = i & 127;
        float raw = g_k[(((size_t)b * 16 + k) << 10) + nc + nn];
        sm_s[k * 128 + nn] = expf(raw - s_mx[k]) * s_mi[k];
    }
    for (int i = tid; i < 64 * 128; i += 256) {
        int vv = i >> 7, nn = i & 127;
        vs_s[nn * 65 + vv] = __half2float(g_vh[(((size_t)b * 64 + vv) << 10) + nc + nn]);
    }
    __syncthreads();
    float acc[16] = {};
    for (int nn = s * 32; nn < s * 32 + 32; nn++) {
        float vv = vs_s[nn * 65 + v];
        #pragma unroll
        for (int k = 0; k < 16; k++) acc[k] += sm_s[k * 128 + nn] * vv;
    }
    __syncthreads();
    #pragma unroll
    for (int k = 0; k < 16; k++) sbuf[s * 1024 + k * 64 + v] = acc[k];
    __syncthreads();
    for (int e = tid; e < 1024; e += 256)
        g_lcp[part][b * 1024 + e] = sbuf[e] + sbuf[1024 + e] + sbuf[2048 + e] + sbuf[3072 + e];
}

// ---------------- K5: lambda_p GEMM (decoupled pipeline + band skip) ----------
#define GEMM_SMEM (1024 + 3 * 65536)

__global__ __launch_bounds__(256) void k_gemm(const float* __restrict__ emb)
{
#if USE_TC
    extern __shared__ char dsm[];
    __shared__ __align__(16) uint64_t s_mbar[3];
    __shared__ uint32_t s_tmem;

    int tid = threadIdx.x;
    int wid = tid >> 5, lane = tid & 31;
    int kg = blockIdx.z;
    int n0 = blockIdx.x * 128;
    int bv0 = blockIdx.y * 256;

    int y0 = blockIdx.x * 4;
    int c_lo = (y0 > 11) ? ((y0 - 11) >> 1) : 0;
    int c_hi = min(15, (y0 + 14) >> 1);
    int nch = c_hi - c_lo + 1;

    uint32_t raw = smem_u32(dsm);
    uint32_t abase = (raw + 1023) & ~1023u;

    if (wid == 0) { TC_ALLOC(smem_u32(&s_tmem), 512); TC_RELINQ(); }
    if (tid == 0) {
        MBAR_INIT(smem_u32(&s_mbar[0]), 1);
        MBAR_INIT(smem_u32(&s_mbar[1]), 1);
        MBAR_INIT(smem_u32(&s_mbar[2]), 1);
    }
    __syncthreads();
    uint32_t tmem = s_tmem;

    const __half* Tk0 = g_T + ((size_t)(2 * kg) << 20);
    const __half* Tk1 = g_T + ((size_t)(2 * kg + 1) << 20);

    #define ISSUE_LOADS(chunk, stage) do {                                            \
        int _m0 = (chunk) * 64;                                                       \
        uint32_t _Sb = abase + (stage) * 65536;                                       \
        for (int _i = tid; _i < 1024; _i += 256) {                                    \
            int _r = _i >> 3, _c = _i & 7;                                            \
            uint32_t _o = _r * 128 + _c * 16;                                         \
            uint32_t _s = _o ^ ((_o >> 3) & 0x70);                                    \
            cpasync16(_Sb + _s, Tk0 + (((size_t)(n0 + _r) << 10) + _m0 + _c * 8));    \
        }                                                                             \
        for (int _i = tid; _i < 1024; _i += 256) {                                    \
            int _r = _i >> 3, _c = _i & 7;                                            \
            uint32_t _o = _r * 128 + _c * 16;                                         \
            uint32_t _s = _o ^ ((_o >> 3) & 0x70);                                    \
            cpasync16(_Sb + 16384 + _s, Tk1 + (((size_t)(n0 + _r) << 10) + _m0 + _c * 8)); \
        }                                                                             \
        for (int _i = tid; _i < 2048; _i += 256) {                                    \
            int _r = _i >> 3, _c = _i & 7;                                            \
            uint32_t _o = _r * 128 + _c * 16;                                         \
            uint32_t _s = _o ^ ((_o >> 3) & 0x70);                                    \
            cpasync16(_Sb + 32768 + _s, g_vh + (((size_t)(bv0 + _r) << 10) + _m0 + _c * 8)); \
        }                                                                             \
    } while (0)

    ISSUE_LOADS(c_lo + 0, 0); CP_COMMIT();
    ISSUE_LOADS(c_lo + 1, 1); CP_COMMIT();
    ISSUE_LOADS(c_lo + 2, 2); CP_COMMIT();

    const uint32_t idesc = (1u << 4) | (32u << 17) | (8u << 24);
    uint32_t php0 = 0, php1 = 0, php2 = 0;

    for (int ci = 0; ci < nch; ci++) {
        int s = ci - (ci / 3) * 3;
        if (ci == 0)            CP_WAIT(2);
        else if (ci == nch - 1) CP_WAIT(0);
        else                    CP_WAIT(1);
        __syncthreads();
        if (wid == 0) {
            FENCE_ASYNC();
            if (elect1()) {
                uint32_t sb = abase + s * 65536;
                uint64_t a0 = mk_desc(sb);
                uint64_t a1 = mk_desc(sb + 16384);
                uint64_t bd = mk_desc(sb + 32768);
                #pragma unroll
                for (int ks = 0; ks < 4; ks++) {
                    uint32_t en = (ci | ks) != 0;
                    mma_f16_ss(tmem,       a0 + ks * 2, bd + ks * 2, idesc, en);
                    mma_f16_ss(tmem + 256, a1 + ks * 2, bd + ks * 2, idesc, en);
                }
                TC_COMMIT(smem_u32(&s_mbar[s]));
            }
        }
        if (ci >= 1 && ci + 2 < nch) {
            int sp = (ci - 1) - ((ci - 1) / 3) * 3;
            uint32_t ph = (sp == 0) ? php0 : (sp == 1) ? php1 : php2;
            MBAR_WAIT(smem_u32(&s_mbar[sp]), ph);
            if (sp == 0) php0 ^= 1; else if (sp == 1) php1 ^= 1; else php2 ^= 1;
            ISSUE_LOADS(c_lo + ci + 2, sp);
            CP_COMMIT();
        }
    }
    MBAR_WAIT(smem_u32(&s_mbar[0]), php0);
    MBAR_WAIT(smem_u32(&s_mbar[1]), php1);
    MBAR_WAIT(smem_u32(&s_mbar[2]), php2);
    TC_FENCE_AFTER();

    int t = wid >> 2;
    int kk = 2 * kg + t;
    int n_g = n0 + (wid & 3) * 32 + lane;
    for (int c0 = 0; c0 < 256; c0 += 32) {
        uint32_t r[32];
        TC_LD_X32(r, tmem + t * 256 + c0);
        TC_WAIT_LD();
        int bvb = bv0 + c0;
        int b = bvb >> 6, vb = bvb & 63;
        uint32_t h2[16];
        #pragma unroll
        for (int j = 0; j < 16; j++) {
            __half2 h = __floats2half2_rn(__uint_as_float(r[2 * j]), __uint_as_float(r[2 * j + 1]));
            h2[j] = *reinterpret_cast<uint32_t*>(&h);
        }
        __half* dst = g_lph + ((((size_t)(b * 16 + kk) << 10) + n_g) << 6) + vb;
        uint4* d4 = reinterpret_cast<uint4*>(dst);
        #pragma unroll
        for (int q4 = 0; q4 < 4; q4++)
            d4[q4] = make_uint4(h2[4 * q4], h2[4 * q4 + 1], h2[4 * q4 + 2], h2[4 * q4 + 3]);
    }
    __syncthreads();
    if (tid == 0) {
        MBAR_INVAL(smem_u32(&s_mbar[0]));
        MBAR_INVAL(smem_u32(&s_mbar[1]));
        MBAR_INVAL(smem_u32(&s_mbar[2]));
    }
    __syncthreads();
    if (wid == 0) TC_DEALLOC(tmem, 512);
    #undef ISSUE_LOADS

#else  // ---- fallback: scalar direct conv ----
    extern __shared__ char dsm[];
    float* img = (float*)dsm;
    float* Es  = img + 54 * 55;
    int tid = threadIdx.x;
    int bid = blockIdx.x + blockIdx.y * 8 + blockIdx.z * 64;

    for (int i = tid; i < 16 * 529; i += 256) Es[i] = emb[i];

    for (int pair = 0; pair < 4; pair++) {
        int bv = bid * 4 + pair;
        int b = bv >> 6, v = bv & 63;
        __syncthreads();
        for (int i = tid; i < 54 * 55; i += 256) img[i] = 0.f;
        __syncthreads();
        float vsc = g_vs[v], vsh = g_vb[v];
        const float* src = g_v + ((size_t)bv << 10);
        for (int i = tid; i < 1024; i += 256) {
            int y = i >> 5, x = i & 31;
            img[(y + PADL) * 55 + x + PADL] = src[i] * vsc + vsh;
        }
        __syncthreads();

        for (int it = 0; it < 4; it++) {
            int task = tid + 256 * it;
            int k = task >> 6;
            int rh = task & 63;
            int row = rh >> 1;
            int xb = (rh & 1) << 4;
            float acc[16] = {};
            const float* ek = Es + k * 529;
            #pragma unroll 1
            for (int i = 0; i < RR; i++) {
                const float* rp = img + (row + i) * 55 + xb;
                float r[38];
                #pragma unroll
                for (int tt = 0; tt < 38; tt++) r[tt] = rp[tt];
                const float* ept = ek + i * RR;
                #pragma unroll
                for (int j = 0; j < RR; j++) {
                    float e = ept[j];
                    #pragma unroll
                    for (int x = 0; x < 16; x++) acc[x] += e * r[j + x];
                }
            }
            int nbase = row * 32 + xb;
            __half* o = g_lph + ((((size_t)(b * 16 + k) << 10) + nbase) << 6) + v;
            #pragma unroll
            for (int x = 0; x < 16; x++) o[(size_t)x << 6] = __float2half(acc[x]);
        }
    }
#endif
}

// ---------------- K6: final contraction (lambda_c reduce fused in) -----------
__global__ __launch_bounds__(256) void k_final(const float* __restrict__ gamma,
                                               float* __restrict__ out)
{
    int b = blockIdx.z;
    int v0 = blockIdx.y * 16;
    int n = blockIdx.x * 256 + threadIdx.x;
    __shared__ float lc_s[256];
    for (int i = threadIdx.x; i < 256; i += 256) {
        int idx = b * 1024 + (i >> 4) * 64 + v0 + (i & 15);
        float sum = 0.f;
        #pragma unroll
        for (int p = 0; p < 8; p++) sum += g_lcp[p][idx];
        lc_s[i] = sum;
    }
    __syncthreads();
    float qv[64];
    #pragma unroll
    for (int ch = 0; ch < 64; ch++)
        qv[ch] = g_q[(((size_t)b * 64 + ch) << 10) + n] * g_qs[ch] + g_qb[ch];
    float gm = 1.f + gamma[0];
    float y[4][16] = {};
    for (int k = 0; k < 16; k++) {
        const __half2* lp = reinterpret_cast<const __half2*>(
            g_lph + ((((size_t)(b * 16 + k) << 10) + n) << 6) + v0);
        float lam[16];
        #pragma unroll
        for (int j = 0; j < 8; j++) {
            float2 f = __half22float2(lp[j]);
            lam[2 * j] = f.x; lam[2 * j + 1] = f.y;
        }
        #pragma unroll
        for (int jj = 0; jj < 16; jj++) lam[jj] += lc_s[k * 16 + jj];
        #pragma unroll
        for (int h = 0; h < 4; h++) {
            float qh = qv[h * 16 + k];
            #pragma unroll
            for (int jj = 0; jj < 16; jj++) y[h][jj] += qh * lam[jj];
        }
    }
    #pragma unroll
    for (int h = 0; h < 4; h++)
        #pragma unroll
        for (int jj = 0; jj < 16; jj++)
            out[(((size_t)b * 256) + h * 64 + v0 + jj) * NN + n] = y[h][jj] * gm;
}

// ---------------- launch ----------------
extern "C" void kernel_launch(void* const* d_in, const int* in_sizes, int n_in,
                              void* d_out, int out_size)
{
    const float* x      = (const float*)d_in[0];
    const float* Wq     = (const float*)d_in[1];
    const float* bn_q_w = (const float*)d_in[2];
    const float* bn_q_b = (const float*)d_in[3];
    const float* Wk     = (const float*)d_in[4];
    const float* Wv     = (const float*)d_in[5];
    const float* bn_v_w = (const float*)d_in[6];
    const float* bn_v_b = (const float*)d_in[7];
    const float* emb    = (const float*)d_in[8];
    const float* gamma  = (const float*)d_in[9];
    float* out = (float*)d_out;

    cudaFuncSetAttribute(k_gemm, cudaFuncAttributeMaxDynamicSharedMemorySize, GEMM_SMEM);
    cudaFuncSetAttribute(k_proj, cudaFuncAttributeMaxDynamicSharedMemorySize, PROJ_SMEM);

    k_prep<<<34976, 256>>>(x, Wq, Wk, Wv, emb);              // 1
    k_proj<<<dim3(4, 32), 256, PROJ_SMEM>>>();               // 2
    k_bnstats<<<128, 256>>>(bn_q_w, bn_q_b, bn_v_w, bn_v_b); // 3
    k_gemm<<<dim3(8, 8, 8), 256, GEMM_SMEM>>>(emb);          // 4  <-- profiled slot
    k_smstats<<<128, 128>>>();                               // 5
    k_lambdac<<<dim3(32, 8), 256>>>();                       // 6
    k_final<<<dim3(4, 4, 32), 256>>>(gamma, out);            // 7
}